// round 10
// baseline (speedup 1.0000x reference)
#include <cuda_runtime.h>
#include <math.h>

#define ND 64
#define ND2 128
#define NHW 4096
#define NBT 64
#define NTT 16
#define NBB 4
#define NTOT (NBT*ND*NHW)
#define PADW 66
#define PLANEP (PADW*PADW)
#define RP 66

typedef unsigned long long u64;

__device__ float g_pad[(size_t)NBT*ND2*PLANEP];   // zero-init: borders stay 0 forever
__device__ float g_a[NTOT], g_b[NTOT], g_c[NTOT], g_d[NTOT];
__device__ float g_w[128*128*9];                  // conv weights transposed [ic*9+tap][oc]
__device__ float g_twr[4096], g_twi[4096];        // DFT twiddle table F[u][w], symmetric

// ---- f32x2 helpers ----
__device__ __forceinline__ u64 pk(float lo, float hi) {
    u64 r; asm("mov.b64 %0, {%1,%2};" : "=l"(r) : "f"(lo), "f"(hi)); return r;
}
__device__ __forceinline__ u64 bc(float v) { return pk(v, v); }
__device__ __forceinline__ void fma2(u64& d, u64 a, u64 b) {
    asm("fma.rn.f32x2 %0, %1, %2, %0;" : "+l"(d) : "l"(a), "l"(b));
}
__device__ __forceinline__ float2 up(u64 v) {
    float2 f; asm("mov.b64 {%0,%1}, %2;" : "=f"(f.x), "=f"(f.y) : "l"(v)); return f;
}
__device__ __forceinline__ u64 lds2(const float* p) { return *(const u64*)p; }
__device__ __forceinline__ u64 ldg2(const float* p) { return *(const u64*)p; }

// ---------- init: conv weight transpose + twiddle table ----------
__global__ void k_init(const float* __restrict__ cw) {
    int i = blockIdx.x*blockDim.x + threadIdx.x;
    if (i < 4096) {
        const float W64 = 6.28318530717958647692f/64.f;
        int u = i>>6, w = i&63, t = (u*w)&63;
        float sv, cv; sincosf(-W64*(float)t, &sv, &cv);
        g_twr[i] = cv; g_twi[i] = sv;
    }
    if (i < 128*128*9) {
        int oc = i / 1152, rem = i - oc*1152;
        g_w[rem*128 + oc] = cw[i];
    }
}

// ---------- spatial complex LayerNorm -> padded buffer ----------
__global__ void k_ln0(const float* __restrict__ xr, const float* __restrict__ xi,
                      const float* __restrict__ gam, const float* __restrict__ bet) {
    __shared__ float s[128][64];
    __shared__ float ps[4][64], pq[4][64], mb[64], rb[64];
    int h = blockIdx.x, n = blockIdx.y;
    int tx = threadIdx.x, ty = threadIdx.y;
    int base = n*(ND*NHW) + h*64 + tx;
    float sum = 0.f, sq = 0.f;
    for (int j = 0; j < 32; j++) {
        int c = ty*32 + j;
        float v = (c < 64) ? xr[base + c*NHW] : xi[base + (c-64)*NHW];
        s[c][tx] = v; sum += v; sq += v*v;
    }
    ps[ty][tx] = sum; pq[ty][tx] = sq;
    __syncthreads();
    if (ty == 0) {
        float S = ps[0][tx]+ps[1][tx]+ps[2][tx]+ps[3][tx];
        float Q = pq[0][tx]+pq[1][tx]+pq[2][tx]+pq[3][tx];
        float m = S*(1.f/128.f);
        mb[tx] = m; rb[tx] = rsqrtf(Q*(1.f/128.f) - m*m + 1e-5f);
    }
    __syncthreads();
    float m = mb[tx], r = rb[tx];
    for (int j = 0; j < 32; j++) {
        int c = ty*32 + j;
        float y = (s[c][tx] - m)*r*gam[c] + bet[c];
        g_pad[((size_t)(n*ND2 + c))*PLANEP + (h+1)*PADW + tx+1] = y;
    }
}

// ---------- merged conv + fft: parity-interleaved blocks mix fma/LDS pipes ----------
// conv smem: 3*16*66 + 16*9*128 = 21600 floats (86.4KB) -- the max
#define CF_SM ((3*16*66 + 16*9*128)*4)

__device__ __forceinline__ void conv_body(float* sm, int h, int n,
                                          const float* __restrict__ cb) {
    float* sin_ = sm;              // [3][16][66]
    float* sw   = sm + 3*16*66;    // [16*9][128]
    int tid = threadIdx.x;
    const float* src = g_pad + (size_t)n*ND2*PLANEP;
    int wg = tid & 15, og = tid >> 4, w0 = wg*4;
    u64 accp[4][4];
    #pragma unroll
    for (int a = 0; a < 4; a++)
        for (int b2 = 0; b2 < 4; b2++) accp[a][b2] = 0ull;
    for (int icc = 0; icc < 8; icc++) {
        __syncthreads();
        for (int l = tid; l < 3*16*66; l += 256) {
            int r = l/(16*66), rem = l - r*(16*66);
            int icl = rem/66, c = rem - icl*66;
            sin_[l] = src[(size_t)(icc*16+icl)*PLANEP + (h + r)*PADW + c];
        }
        for (int l = tid; l < 16*9*128; l += 256)
            sw[l] = g_w[icc*16*9*128 + l];
        __syncthreads();
        #pragma unroll 1
        for (int icl = 0; icl < 16; icl++) {
            float inv[3][6];
            #pragma unroll
            for (int r = 0; r < 3; r++) {
                float2 t0 = *(const float2*)&sin_[(r*16+icl)*66 + w0];
                float2 t1 = *(const float2*)&sin_[(r*16+icl)*66 + w0 + 2];
                float2 t2 = *(const float2*)&sin_[(r*16+icl)*66 + w0 + 4];
                inv[r][0]=t0.x; inv[r][1]=t0.y; inv[r][2]=t1.x;
                inv[r][3]=t1.y; inv[r][4]=t2.x; inv[r][5]=t2.y;
            }
            #pragma unroll
            for (int ky = 0; ky < 3; ky++)
                for (int kx = 0; kx < 3; kx++) {
                    int tap = ky*3 + kx;
                    u64 b0 = bc(inv[ky][kx]),   b1 = bc(inv[ky][kx+1]);
                    u64 b2 = bc(inv[ky][kx+2]), b3 = bc(inv[ky][kx+3]);
                    const u64* wp = (const u64*)&sw[(icl*9+tap)*128 + og*8];
                    #pragma unroll
                    for (int op = 0; op < 4; op++) {
                        u64 wv = wp[op];
                        fma2(accp[op][0], wv, b0);
                        fma2(accp[op][1], wv, b1);
                        fma2(accp[op][2], wv, b2);
                        fma2(accp[op][3], wv, b3);
                    }
                }
        }
    }
    int ob = n*(ND*NHW) + h*64 + w0;
    #pragma unroll
    for (int op = 0; op < 4; op++) {
        int oc0 = og*8 + 2*op;
        float bia0 = cb[oc0], bia1 = cb[oc0+1];
        float2 v0 = up(accp[op][0]), v1 = up(accp[op][1]);
        float2 v2 = up(accp[op][2]), v3 = up(accp[op][3]);
        float4 a4 = make_float4(v0.x+bia0, v1.x+bia0, v2.x+bia0, v3.x+bia0);
        float4 b4 = make_float4(v0.y+bia1, v1.y+bia1, v2.y+bia1, v3.y+bia1);
        if (oc0 < 64) {
            *(float4*)&g_a[ob + oc0*NHW]     = a4;
            *(float4*)&g_a[ob + (oc0+1)*NHW] = b4;
        } else {
            *(float4*)&g_b[ob + (oc0-64)*NHW] = a4;
            *(float4*)&g_b[ob + (oc0-63)*NHW] = b4;
        }
    }
}

__device__ __forceinline__ void fft_body(float* sm, int d, int n,
                                         const float* __restrict__ swr,
                                         const float* __restrict__ swi) {
    float *ar = sm, *ai = ar+64*RP, *br = ai+64*RP, *bi = br+64*RP;
    int tid = threadIdx.x;
    const float* pr0 = g_pad + ((size_t)(n*ND2 + d))*PLANEP;
    const float* pi0 = g_pad + ((size_t)(n*ND2 + 64 + d))*PLANEP;
    for (int l = tid; l < 4096; l += 256) {
        int hh = l>>6, ww = l&63;
        ar[hh*RP+ww] = pr0[(hh+1)*PADW + ww+1];
        ai[hh*RP+ww] = pi0[(hh+1)*PADW + ww+1];
    }
    __syncthreads();
    int r0 = (tid>>4)*4, c0 = (tid&15)*4;
    { // pass1
        u64 pr_[4][2] = {}, pi_[4][2] = {};
        for (int w = 0; w < 64; w++) {
            u64 g0 = ldg2(&g_twr[w*64+c0]), g1 = ldg2(&g_twr[w*64+c0+2]);
            u64 q0 = ldg2(&g_twi[w*64+c0]), q1 = ldg2(&g_twi[w*64+c0+2]);
            #pragma unroll
            for (int i = 0; i < 4; i++) {
                float xr1 = ar[(r0+i)*RP+w], xi1 = ai[(r0+i)*RP+w];
                u64 bxr = bc(xr1), bxi = bc(xi1), bnxi = bc(-xi1);
                fma2(pr_[i][0], bxr, g0); fma2(pr_[i][0], bnxi, q0);
                fma2(pr_[i][1], bxr, g1); fma2(pr_[i][1], bnxi, q1);
                fma2(pi_[i][0], bxr, q0); fma2(pi_[i][0], bxi, g0);
                fma2(pi_[i][1], bxr, q1); fma2(pi_[i][1], bxi, g1);
            }
        }
        #pragma unroll
        for (int i = 0; i < 4; i++) {
            *(float2*)&br[(r0+i)*RP+c0]   = up(pr_[i][0]);
            *(float2*)&br[(r0+i)*RP+c0+2] = up(pr_[i][1]);
            *(float2*)&bi[(r0+i)*RP+c0]   = up(pi_[i][0]);
            *(float2*)&bi[(r0+i)*RP+c0+2] = up(pi_[i][1]);
        }
    }
    __syncthreads();
    { // pass2
        u64 pr_[4][2] = {}, pi_[4][2] = {};
        for (int hs = 0; hs < 64; hs++) {
            u64 x0 = lds2(&br[hs*RP+c0]), x1 = lds2(&br[hs*RP+c0+2]);
            u64 y0 = lds2(&bi[hs*RP+c0]), y1 = lds2(&bi[hs*RP+c0+2]);
            float2 ga = *(const float2*)&g_twr[hs*64+r0], gb2 = *(const float2*)&g_twr[hs*64+r0+2];
            float2 qa = *(const float2*)&g_twi[hs*64+r0], qb = *(const float2*)&g_twi[hs*64+r0+2];
            float grs[4] = {ga.x, ga.y, gb2.x, gb2.y};
            float gis[4] = {qa.x, qa.y, qb.x, qb.y};
            #pragma unroll
            for (int i = 0; i < 4; i++) {
                u64 bgr = bc(grs[i]), bgi = bc(gis[i]), bngi = bc(-gis[i]);
                fma2(pr_[i][0], bgr, x0); fma2(pr_[i][0], bngi, y0);
                fma2(pr_[i][1], bgr, x1); fma2(pr_[i][1], bngi, y1);
                fma2(pi_[i][0], bgr, y0); fma2(pi_[i][0], bgi, x0);
                fma2(pi_[i][1], bgr, y1); fma2(pi_[i][1], bgi, x1);
            }
        }
        __syncthreads();
        #pragma unroll
        for (int i = 0; i < 4; i++) {
            *(float2*)&ar[(r0+i)*RP+c0]   = up(pr_[i][0]);
            *(float2*)&ar[(r0+i)*RP+c0+2] = up(pr_[i][1]);
            *(float2*)&ai[(r0+i)*RP+c0]   = up(pi_[i][0]);
            *(float2*)&ai[(r0+i)*RP+c0+2] = up(pi_[i][1]);
        }
    }
    __syncthreads();
    { // pointwise * spec_w[d]
        const float* wr2 = swr + d*NHW; const float* wi2 = swi + d*NHW;
        for (int l = tid; l < 4096; l += 256) {
            int u = l>>6, v = l&63;
            float zr = ar[u*RP+v], zi = ai[u*RP+v];
            float wr_ = wr2[l], wi_ = wi2[l];
            ar[u*RP+v] = zr*wr_ - zi*wi_;
            ai[u*RP+v] = zr*wi_ + zi*wr_;
        }
    }
    __syncthreads();
    { // pass3
        u64 pr_[4][2] = {}, pi_[4][2] = {};
        for (int us = 0; us < 64; us++) {
            u64 x0 = lds2(&ar[us*RP+c0]), x1 = lds2(&ar[us*RP+c0+2]);
            u64 y0 = lds2(&ai[us*RP+c0]), y1 = lds2(&ai[us*RP+c0+2]);
            float2 ga = *(const float2*)&g_twr[us*64+r0], gb2 = *(const float2*)&g_twr[us*64+r0+2];
            float2 qa = *(const float2*)&g_twi[us*64+r0], qb = *(const float2*)&g_twi[us*64+r0+2];
            float grs[4] = {ga.x, ga.y, gb2.x, gb2.y};
            float gis[4] = {qa.x, qa.y, qb.x, qb.y};
            #pragma unroll
            for (int i = 0; i < 4; i++) {
                u64 bgr = bc(grs[i]), bgi = bc(gis[i]), bngi = bc(-gis[i]);
                fma2(pr_[i][0], bgr, x0); fma2(pr_[i][0], bgi, y0);
                fma2(pr_[i][1], bgr, x1); fma2(pr_[i][1], bgi, y1);
                fma2(pi_[i][0], bgr, y0); fma2(pi_[i][0], bngi, x0);
                fma2(pi_[i][1], bgr, y1); fma2(pi_[i][1], bngi, x1);
            }
        }
        #pragma unroll
        for (int i = 0; i < 4; i++) {
            *(float2*)&br[(r0+i)*RP+c0]   = up(pr_[i][0]);
            *(float2*)&br[(r0+i)*RP+c0+2] = up(pr_[i][1]);
            *(float2*)&bi[(r0+i)*RP+c0]   = up(pi_[i][0]);
            *(float2*)&bi[(r0+i)*RP+c0+2] = up(pi_[i][1]);
        }
    }
    __syncthreads();
    { // pass4 -> spec (scaled) to g_c/g_d
        u64 pr_[4][2] = {}, pi_[4][2] = {};
        for (int vs = 0; vs < 64; vs++) {
            u64 g0 = ldg2(&g_twr[vs*64+c0]), g1 = ldg2(&g_twr[vs*64+c0+2]);
            u64 q0 = ldg2(&g_twi[vs*64+c0]), q1 = ldg2(&g_twi[vs*64+c0+2]);
            #pragma unroll
            for (int i = 0; i < 4; i++) {
                float xr1 = br[(r0+i)*RP+vs], xi1 = bi[(r0+i)*RP+vs];
                u64 bxr = bc(xr1), bxi = bc(xi1), bnxr = bc(-xr1);
                fma2(pr_[i][0], bxr, g0); fma2(pr_[i][0], bxi, q0);
                fma2(pr_[i][1], bxr, g1); fma2(pr_[i][1], bxi, q1);
                fma2(pi_[i][0], bxi, g0); fma2(pi_[i][0], bnxr, q0);
                fma2(pi_[i][1], bxi, g1); fma2(pi_[i][1], bnxr, q1);
            }
        }
        const float sc = 1.f/4096.f;
        int base = n*ND*NHW + d*NHW;
        #pragma unroll
        for (int i = 0; i < 4; i++)
            for (int jp = 0; jp < 2; jp++) {
                int idx = base + (r0+i)*64 + c0 + 2*jp;
                float2 sr = up(pr_[i][jp]);
                float2 si = up(pi_[i][jp]);
                sr.x *= sc; sr.y *= sc; si.x *= sc; si.y *= sc;
                *(float2*)&g_c[idx] = sr;
                *(float2*)&g_d[idx] = si;
            }
    }
}

__global__ __launch_bounds__(256, 2) void k_convfft(const float* __restrict__ cb,
                                                    const float* __restrict__ swr,
                                                    const float* __restrict__ swi) {
    extern __shared__ float sm[];
    int bid = blockIdx.x;
    int c = bid >> 1;
    int hd = c & 63, n = c >> 6;
    if (bid & 1) fft_body(sm, hd, n, swr, swi);
    else         conv_body(sm, hd, n, cb);
}

// ---------- combine: x1 = g*cliff + (1-g)*spec + x_in -> g_a/g_b ----------
__global__ void k_comb(const float* __restrict__ xr, const float* __restrict__ xi,
                       const float* __restrict__ gate) {
    int i = (blockIdx.x*blockDim.x + threadIdx.x) * 4;
    float g = gate[0], omg = 1.f - g;
    float4 a = *(float4*)&g_a[i];
    float4 c = *(float4*)&g_c[i];
    float4 x = *(const float4*)&xr[i];
    a.x = g*a.x + omg*c.x + x.x;  a.y = g*a.y + omg*c.y + x.y;
    a.z = g*a.z + omg*c.z + x.z;  a.w = g*a.w + omg*c.w + x.w;
    *(float4*)&g_a[i] = a;
    float4 b = *(float4*)&g_b[i];
    float4 d = *(float4*)&g_d[i];
    float4 y = *(const float4*)&xi[i];
    b.x = g*b.x + omg*d.x + y.x;  b.y = g*b.y + omg*d.y + y.y;
    b.z = g*b.z + omg*d.z + y.z;  b.w = g*b.w + omg*d.w + y.w;
    *(float4*)&g_b[i] = b;
}

// ---------- fused temporal branch: LN + encode + recurrence + decode + resid ----------
#define TEMP_SM (6*64*RP*4)
__global__ __launch_bounds__(256, 2) void k_temporal(
        const float* __restrict__ er, const float* __restrict__ ei,
        const float* __restrict__ dmr, const float* __restrict__ dmi,
        const float* __restrict__ gam, const float* __restrict__ bet,
        const float* __restrict__ dt,  const float* __restrict__ lr_,
        const float* __restrict__ li_) {
    extern __shared__ float sm[];
    float *Er = sm, *Ei = Er+64*RP, *Dr = Ei+64*RP, *Di = Dr+64*RP;
    float *Xr = Di+64*RP, *Xi = Xr+64*RP;
    __shared__ float ps[4][64], pq[4][64], mb[64], rb[64];
    int pt = blockIdx.x, b = blockIdx.y, tid = threadIdx.x, hw0 = pt*64;
    for (int l = tid; l < 4096; l += 256) {
        int r_ = l>>6, c_ = l&63;
        Er[r_*RP+c_] = er[l];  Ei[r_*RP+c_] = ei[l];
        Dr[r_*RP+c_] = dmr[l]; Di[r_*RP+c_] = dmi[l];
    }
    int e0 = (tid>>4)*4, p0 = (tid&15)*4;
    float ddr[4], ddi[4], ffr[4], ffi[4];
    float dtb = dt[b];
    #pragma unroll
    for (int i = 0; i < 4; i++) {
        float lr = lr_[e0+i], li = li_[e0+i];
        float ex = expf(lr*dtb);
        float sn, cs; sincosf(li*dtb, &sn, &cs);
        ddr[i] = ex*cs; ddi[i] = ex*sn;
        float nr = ddr[i]-1.f, ni = ddi[i];
        float den = 1.f/(lr*lr + li*li);
        ffr[i] = (nr*lr + ni*li)*den;
        ffi[i] = (ni*lr - nr*li)*den;
    }
    u64 hrp[4][2] = {}, hip[4][2] = {};
    int lnp = tid & 63;
    for (int t = 0; t < NTT; t++) {
        int n = b*NTT + t;
        __syncthreads();
        float sum = 0.f, sq = 0.f;
        for (int l = tid; l < 4096; l += 256) {
            int dd = l>>6, p = l&63;
            int gi_ = (n*ND+dd)*NHW + hw0 + p;
            float vr = g_a[gi_], vi = g_b[gi_];
            Xr[dd*RP+p] = vr; Xi[dd*RP+p] = vi;
            sum += vr + vi; sq += vr*vr + vi*vi;
        }
        ps[tid>>6][lnp] = sum; pq[tid>>6][lnp] = sq;
        __syncthreads();
        if (tid < 64) {
            float S = ps[0][tid]+ps[1][tid]+ps[2][tid]+ps[3][tid];
            float Q = pq[0][tid]+pq[1][tid]+pq[2][tid]+pq[3][tid];
            float m = S*(1.f/128.f);
            mb[tid] = m; rb[tid] = rsqrtf(Q*(1.f/128.f) - m*m + 1e-5f);
        }
        __syncthreads();
        {
            float m = mb[lnp], r = rb[lnp];
            for (int l = tid; l < 4096; l += 256) {
                int dd = l>>6, p = l&63;
                Xr[dd*RP+p] = (Xr[dd*RP+p] - m)*r*gam[dd]    + bet[dd];
                Xi[dd*RP+p] = (Xi[dd*RP+p] - m)*r*gam[dd+64] + bet[dd+64];
            }
        }
        __syncthreads();
        u64 pr_[4][2] = {}, pi_[4][2] = {};
        for (int dd = 0; dd < 64; dd++) {
            u64 x0 = lds2(&Xr[dd*RP+p0]), x1 = lds2(&Xr[dd*RP+p0+2]);
            u64 y0 = lds2(&Xi[dd*RP+p0]), y1 = lds2(&Xi[dd*RP+p0+2]);
            float2 ea = *(const float2*)&Er[dd*RP+e0], eb = *(const float2*)&Er[dd*RP+e0+2];
            float2 qa = *(const float2*)&Ei[dd*RP+e0], qb = *(const float2*)&Ei[dd*RP+e0+2];
            float ers[4] = {ea.x, ea.y, eb.x, eb.y};
            float eis[4] = {qa.x, qa.y, qb.x, qb.y};
            #pragma unroll
            for (int i = 0; i < 4; i++) {
                u64 ber = bc(ers[i]), bei = bc(eis[i]), bnei = bc(-eis[i]);
                fma2(pr_[i][0], x0, ber); fma2(pr_[i][0], y0, bnei);
                fma2(pr_[i][1], x1, ber); fma2(pr_[i][1], y1, bnei);
                fma2(pi_[i][0], x0, bei); fma2(pi_[i][0], y0, ber);
                fma2(pi_[i][1], x1, bei); fma2(pi_[i][1], y1, ber);
            }
        }
        #pragma unroll
        for (int i = 0; i < 4; i++) {
            u64 bdr = bc(ddr[i]), bdi = bc(ddi[i]), bndi = bc(-ddi[i]);
            u64 bfr = bc(ffr[i]), bfi = bc(ffi[i]), bnfi = bc(-ffi[i]);
            #pragma unroll
            for (int jp = 0; jp < 2; jp++) {
                u64 nr_ = 0ull, ni_ = 0ull;
                fma2(nr_, hrp[i][jp], bdr); fma2(nr_, hip[i][jp], bndi);
                fma2(nr_, pr_[i][jp], bfr); fma2(nr_, pi_[i][jp], bnfi);
                fma2(ni_, hrp[i][jp], bdi); fma2(ni_, hip[i][jp], bdr);
                fma2(ni_, pr_[i][jp], bfi); fma2(ni_, pi_[i][jp], bfr);
                hrp[i][jp] = nr_; hip[i][jp] = ni_;
            }
        }
        __syncthreads();
        #pragma unroll
        for (int i = 0; i < 4; i++)
            for (int jp = 0; jp < 2; jp++) {
                *(float2*)&Xr[(e0+i)*RP + p0 + 2*jp] = up(hrp[i][jp]);
                *(float2*)&Xi[(e0+i)*RP + p0 + 2*jp] = up(hip[i][jp]);
            }
        __syncthreads();
        u64 acc[4][2] = {};
        for (int e = 0; e < 64; e++) {
            u64 x0 = lds2(&Xr[e*RP+p0]), x1 = lds2(&Xr[e*RP+p0+2]);
            u64 y0 = lds2(&Xi[e*RP+p0]), y1 = lds2(&Xi[e*RP+p0+2]);
            float2 da = *(const float2*)&Dr[e*RP+e0], db = *(const float2*)&Dr[e*RP+e0+2];
            float2 qa = *(const float2*)&Di[e*RP+e0], qb = *(const float2*)&Di[e*RP+e0+2];
            float drs[4] = {da.x, da.y, db.x, db.y};
            float dis[4] = {qa.x, qa.y, qb.x, qb.y};
            #pragma unroll
            for (int i = 0; i < 4; i++) {
                u64 bdr = bc(drs[i]), bnd = bc(-dis[i]);
                fma2(acc[i][0], x0, bdr); fma2(acc[i][0], y0, bnd);
                fma2(acc[i][1], x1, bdr); fma2(acc[i][1], y1, bnd);
            }
        }
        #pragma unroll
        for (int i = 0; i < 4; i++)
            for (int jp = 0; jp < 2; jp++) {
                int gi_ = (n*ND + e0+i)*NHW + hw0 + p0 + 2*jp;
                float2 v = up(acc[i][jp]);
                float2 rs = *(const float2*)&g_a[gi_];
                v.x += rs.x; v.y += rs.y;
                *(float2*)&g_c[gi_] = v;
            }
    }
}

// ---------- fast gelu ----------
__device__ __forceinline__ float gelu_f(float x) {
    float u = 0.7978845608028654f*(x + 0.044715f*x*x*x);
    return x * (1.f - __fdividef(1.f, __expf(2.f*u) + 1.f));
}

// ---------- fused MLP 128 -> 512(gelu) -> 128 + residual, f chunked by 64 ----------
#define MLP_SM ((128*66 + 64*66 + 8448)*4)
__global__ __launch_bounds__(256) void k_mlp(const float* __restrict__ w1,
                                             const float* __restrict__ b1,
                                             const float* __restrict__ w2,
                                             const float* __restrict__ b2,
                                             float* __restrict__ out) {
    extern __shared__ float sm[];
    float *Xs = sm;
    float *Hs = Xs + 128*66;
    float *Ws = Hs + 64*66;
    int pt = blockIdx.x, n = blockIdx.y, tid = threadIdx.x, hw0 = pt*64;
    for (int l = tid; l < 128*64; l += 256) {
        int c = l>>6, p = l&63;
        float v = (c < 64) ? g_c[(n*ND+c)*NHW + hw0 + p]
                           : g_b[(n*ND+c-64)*NHW + hw0 + p];
        Xs[c*66+p] = v;
    }
    int fg = (tid>>4)*4, p0 = (tid&15)*4;
    int c8 = (tid>>4)*8;
    u64 accp[4][4];
    #pragma unroll
    for (int i = 0; i < 4; i++)
        for (int j = 0; j < 4; j++) accp[i][j] = 0ull;
    for (int fc = 0; fc < 8; fc++) {
        __syncthreads();
        for (int l = tid; l < 128*64; l += 256) {
            int c = l>>6, f = l&63;
            Ws[c*66+f] = w1[c*512 + fc*64 + f];
        }
        __syncthreads();
        u64 a2p[2][4];
        #pragma unroll
        for (int i = 0; i < 2; i++)
            for (int j = 0; j < 4; j++) a2p[i][j] = 0ull;
        for (int c = 0; c < 128; c++) {
            float2 x01 = *(const float2*)&Xs[c*66+p0];
            float2 x23 = *(const float2*)&Xs[c*66+p0+2];
            u64 bx[4] = {bc(x01.x), bc(x01.y), bc(x23.x), bc(x23.y)};
            u64 w01 = lds2(&Ws[c*66+fg]), w23 = lds2(&Ws[c*66+fg+2]);
            fma2(a2p[0][0], w01, bx[0]); fma2(a2p[0][1], w01, bx[1]);
            fma2(a2p[0][2], w01, bx[2]); fma2(a2p[0][3], w01, bx[3]);
            fma2(a2p[1][0], w23, bx[0]); fma2(a2p[1][1], w23, bx[1]);
            fma2(a2p[1][2], w23, bx[2]); fma2(a2p[1][3], w23, bx[3]);
        }
        __syncthreads();
        #pragma unroll
        for (int ip = 0; ip < 2; ip++) {
            int fA = fg + 2*ip, fB = fA + 1;
            float biasA = b1[fc*64 + fA], biasB = b1[fc*64 + fB];
            float2 v0 = up(a2p[ip][0]), v1 = up(a2p[ip][1]);
            float2 v2 = up(a2p[ip][2]), v3 = up(a2p[ip][3]);
            Hs[fA*66 + p0]   = gelu_f(v0.x + biasA);
            Hs[fA*66 + p0+1] = gelu_f(v1.x + biasA);
            Hs[fA*66 + p0+2] = gelu_f(v2.x + biasA);
            Hs[fA*66 + p0+3] = gelu_f(v3.x + biasA);
            Hs[fB*66 + p0]   = gelu_f(v0.y + biasB);
            Hs[fB*66 + p0+1] = gelu_f(v1.y + biasB);
            Hs[fB*66 + p0+2] = gelu_f(v2.y + biasB);
            Hs[fB*66 + p0+3] = gelu_f(v3.y + biasB);
        }
        for (int l = tid; l < 64*128; l += 256) {
            int f = l>>7, c = l&127;
            Ws[f*130+c] = w2[(fc*64+f)*128 + c];
        }
        __syncthreads();
        for (int f = 0; f < 64; f++) {
            float2 h01 = *(const float2*)&Hs[f*66+p0];
            float2 h23 = *(const float2*)&Hs[f*66+p0+2];
            u64 bh[4] = {bc(h01.x), bc(h01.y), bc(h23.x), bc(h23.y)};
            const u64* wp = (const u64*)&Ws[f*130+c8];
            #pragma unroll
            for (int ip = 0; ip < 4; ip++) {
                u64 wv = wp[ip];
                fma2(accp[ip][0], wv, bh[0]); fma2(accp[ip][1], wv, bh[1]);
                fma2(accp[ip][2], wv, bh[2]); fma2(accp[ip][3], wv, bh[3]);
            }
        }
    }
    #pragma unroll
    for (int ip = 0; ip < 4; ip++) {
        int cA = c8 + 2*ip, cB = cA + 1;
        float bA = b2[cA], bB = b2[cB];
        #pragma unroll
        for (int j = 0; j < 4; j++) {
            float2 v = up(accp[ip][j]);
            int p = p0 + j;
            float resA = (cA < 64) ? g_c[(n*ND+cA)*NHW + hw0 + p]
                                   : g_b[(n*ND+cA-64)*NHW + hw0 + p];
            float resB = (cB < 64) ? g_c[(n*ND+cB)*NHW + hw0 + p]
                                   : g_b[(n*ND+cB-64)*NHW + hw0 + p];
            out[((size_t)n*ND2 + cA)*NHW + hw0 + p] = v.x + bA + resA;
            out[((size_t)n*ND2 + cB)*NHW + hw0 + p] = v.y + bB + resB;
        }
    }
}

extern "C" void kernel_launch(void* const* d_in, const int* in_sizes, int n_in,
                              void* d_out, int out_size) {
    const float* xr   = (const float*)d_in[0];
    const float* xi   = (const float*)d_in[1];
    const float* dt   = (const float*)d_in[2];
    const float* lsg  = (const float*)d_in[3];
    const float* lsb  = (const float*)d_in[4];
    const float* cw   = (const float*)d_in[5];
    const float* cb   = (const float*)d_in[6];
    const float* swr  = (const float*)d_in[7];
    const float* swi  = (const float*)d_in[8];
    const float* gate = (const float*)d_in[9];
    const float* ltg  = (const float*)d_in[10];
    const float* ltb  = (const float*)d_in[11];
    const float* lamr = (const float*)d_in[12];
    const float* lami = (const float*)d_in[13];
    const float* enr  = (const float*)d_in[14];
    const float* eni  = (const float*)d_in[15];
    const float* dcr  = (const float*)d_in[16];
    const float* dci  = (const float*)d_in[17];
    const float* w1   = (const float*)d_in[18];
    const float* b1   = (const float*)d_in[19];
    const float* w2   = (const float*)d_in[20];
    const float* b2   = (const float*)d_in[21];
    float* out = (float*)d_out;

    cudaFuncSetAttribute(k_convfft,  cudaFuncAttributeMaxDynamicSharedMemorySize, CF_SM);
    cudaFuncSetAttribute(k_temporal, cudaFuncAttributeMaxDynamicSharedMemorySize, TEMP_SM);
    cudaFuncSetAttribute(k_mlp,      cudaFuncAttributeMaxDynamicSharedMemorySize, MLP_SM);

    dim3 gHN(64, 64);
    k_init<<<(128*128*9 + 255)/256, 256>>>(cw);
    k_ln0<<<gHN, dim3(64,4)>>>(xr, xi, lsg, lsb);
    k_convfft<<<8192, 256, CF_SM>>>(cb, swr, swi);
    k_comb<<<NTOT/1024, 256>>>(xr, xi, gate);
    k_temporal<<<dim3(64, NBB), 256, TEMP_SM>>>(enr, eni, dcr, dci, ltg, ltb, dt, lamr, lami);
    k_mlp<<<gHN, 256, MLP_SM>>>(w1, b1, w2, b2, out);
}

// round 11
// speedup vs baseline: 1.0579x; 1.0579x over previous
#include <cuda_runtime.h>
#include <math.h>

#define ND 64
#define ND2 128
#define NHW 4096
#define NBT 64
#define NTT 16
#define NBB 4
#define NTOT (NBT*ND*NHW)
#define PADW 66
#define PLANEP (PADW*PADW)
#define RP 66

typedef unsigned long long u64;

__device__ float g_pad[(size_t)NBT*ND2*PLANEP];   // zero-init: borders stay 0 forever
__device__ float g_a[NTOT], g_b[NTOT], g_c[NTOT], g_d[NTOT];
__device__ float g_w[128*128*9];                  // conv weights transposed [ic*9+tap][oc]
__device__ float g_twr[4096], g_twi[4096], g_twin[4096];  // DFT twiddles: cos, sin, -sin

// ---- f32x2 helpers ----
__device__ __forceinline__ u64 pk(float lo, float hi) {
    u64 r; asm("mov.b64 %0, {%1,%2};" : "=l"(r) : "f"(lo), "f"(hi)); return r;
}
__device__ __forceinline__ u64 bc(float v) { return pk(v, v); }
__device__ __forceinline__ void fma2(u64& d, u64 a, u64 b) {
    asm("fma.rn.f32x2 %0, %1, %2, %0;" : "+l"(d) : "l"(a), "l"(b));
}
__device__ __forceinline__ float2 up(u64 v) {
    float2 f; asm("mov.b64 {%0,%1}, %2;" : "=f"(f.x), "=f"(f.y) : "l"(v)); return f;
}
__device__ __forceinline__ u64 lds2(const float* p) { return *(const u64*)p; }
__device__ __forceinline__ u64 ldg2(const float* p) { return *(const u64*)p; }

// ---------- init ----------
__global__ void k_init(const float* __restrict__ cw) {
    int i = blockIdx.x*blockDim.x + threadIdx.x;
    if (i < 4096) {
        const float W64 = 6.28318530717958647692f/64.f;
        int u = i>>6, w = i&63, t = (u*w)&63;
        float sv, cv; sincosf(-W64*(float)t, &sv, &cv);
        g_twr[i] = cv; g_twi[i] = sv; g_twin[i] = -sv;
    }
    if (i < 128*128*9) {
        int oc = i / 1152, rem = i - oc*1152;
        g_w[rem*128 + oc] = cw[i];
    }
}

// ---------- spatial complex LayerNorm -> padded buffer ----------
__global__ void k_ln0(const float* __restrict__ xr, const float* __restrict__ xi,
                      const float* __restrict__ gam, const float* __restrict__ bet) {
    __shared__ float s[128][64];
    __shared__ float ps[4][64], pq[4][64], mb[64], rb[64];
    int h = blockIdx.x, n = blockIdx.y;
    int tx = threadIdx.x, ty = threadIdx.y;
    int base = n*(ND*NHW) + h*64 + tx;
    float sum = 0.f, sq = 0.f;
    for (int j = 0; j < 32; j++) {
        int c = ty*32 + j;
        float v = (c < 64) ? xr[base + c*NHW] : xi[base + (c-64)*NHW];
        s[c][tx] = v; sum += v; sq += v*v;
    }
    ps[ty][tx] = sum; pq[ty][tx] = sq;
    __syncthreads();
    if (ty == 0) {
        float S = ps[0][tx]+ps[1][tx]+ps[2][tx]+ps[3][tx];
        float Q = pq[0][tx]+pq[1][tx]+pq[2][tx]+pq[3][tx];
        float m = S*(1.f/128.f);
        mb[tx] = m; rb[tx] = rsqrtf(Q*(1.f/128.f) - m*m + 1e-5f);
    }
    __syncthreads();
    float m = mb[tx], r = rb[tx];
    for (int j = 0; j < 32; j++) {
        int c = ty*32 + j;
        float y = (s[c][tx] - m)*r*gam[c] + bet[c];
        g_pad[((size_t)(n*ND2 + c))*PLANEP + (h+1)*PADW + tx+1] = y;
    }
}

// ---------- merged conv(2 rows/block) + fft ----------
#define CF_SM ((4*16*68 + 16*9*128)*4)

__device__ __forceinline__ void conv_body(float* sm, int hb, int n,
                                          const float* __restrict__ cb) {
    float* sin_ = sm;              // [4][16][68]  rows h0..h0+3 per ic chunk
    float* sw   = sm + 4*16*68;    // [16*9][128]
    int tid = threadIdx.x;
    int h0 = hb*2;
    const float* src = g_pad + (size_t)n*ND2*PLANEP;
    int wg = tid & 15, og = tid >> 4, w0 = wg*4;
    u64 accp[2][4][4];
    #pragma unroll
    for (int hh = 0; hh < 2; hh++)
        for (int a = 0; a < 4; a++)
            for (int b2 = 0; b2 < 4; b2++) accp[hh][a][b2] = 0ull;
    for (int icc = 0; icc < 8; icc++) {
        __syncthreads();
        for (int l = tid; l < 4*16*68; l += 256) {
            int r = l/(16*68), rem = l - r*(16*68);
            int icl = rem/68, c = rem - icl*68;
            sin_[l] = (c < 66) ? src[(size_t)(icc*16+icl)*PLANEP + (h0 + r)*PADW + c] : 0.f;
        }
        for (int l = tid; l < 16*9*128; l += 256)
            sw[l] = g_w[icc*16*9*128 + l];
        __syncthreads();
        #pragma unroll 1
        for (int icl = 0; icl < 16; icl++) {
            float inv[4][6];
            #pragma unroll
            for (int r = 0; r < 4; r++) {
                const float* rp = &sin_[(r*16+icl)*68 + w0];
                float4 q = *(const float4*)rp;
                float2 t = *(const float2*)(rp+4);
                inv[r][0]=q.x; inv[r][1]=q.y; inv[r][2]=q.z;
                inv[r][3]=q.w; inv[r][4]=t.x; inv[r][5]=t.y;
            }
            #pragma unroll
            for (int ky = 0; ky < 3; ky++)
                for (int kx = 0; kx < 3; kx++) {
                    int tap = ky*3 + kx;
                    const u64* wp = (const u64*)&sw[(icl*9+tap)*128 + og*8];
                    u64 wv0 = wp[0], wv1 = wp[1], wv2 = wp[2], wv3 = wp[3];
                    #pragma unroll
                    for (int hh = 0; hh < 2; hh++) {
                        u64 b0 = bc(inv[ky+hh][kx]),   b1 = bc(inv[ky+hh][kx+1]);
                        u64 b2 = bc(inv[ky+hh][kx+2]), b3 = bc(inv[ky+hh][kx+3]);
                        fma2(accp[hh][0][0], wv0, b0); fma2(accp[hh][0][1], wv0, b1);
                        fma2(accp[hh][0][2], wv0, b2); fma2(accp[hh][0][3], wv0, b3);
                        fma2(accp[hh][1][0], wv1, b0); fma2(accp[hh][1][1], wv1, b1);
                        fma2(accp[hh][1][2], wv1, b2); fma2(accp[hh][1][3], wv1, b3);
                        fma2(accp[hh][2][0], wv2, b0); fma2(accp[hh][2][1], wv2, b1);
                        fma2(accp[hh][2][2], wv2, b2); fma2(accp[hh][2][3], wv2, b3);
                        fma2(accp[hh][3][0], wv3, b0); fma2(accp[hh][3][1], wv3, b1);
                        fma2(accp[hh][3][2], wv3, b2); fma2(accp[hh][3][3], wv3, b3);
                    }
                }
        }
    }
    #pragma unroll
    for (int hh = 0; hh < 2; hh++) {
        int ob = n*(ND*NHW) + (h0+hh)*64 + w0;
        #pragma unroll
        for (int op = 0; op < 4; op++) {
            int oc0 = og*8 + 2*op;
            float bia0 = cb[oc0], bia1 = cb[oc0+1];
            float2 v0 = up(accp[hh][op][0]), v1 = up(accp[hh][op][1]);
            float2 v2 = up(accp[hh][op][2]), v3 = up(accp[hh][op][3]);
            float4 a4 = make_float4(v0.x+bia0, v1.x+bia0, v2.x+bia0, v3.x+bia0);
            float4 b4 = make_float4(v0.y+bia1, v1.y+bia1, v2.y+bia1, v3.y+bia1);
            if (oc0 < 64) {
                *(float4*)&g_a[ob + oc0*NHW]     = a4;
                *(float4*)&g_a[ob + (oc0+1)*NHW] = b4;
            } else {
                *(float4*)&g_b[ob + (oc0-64)*NHW] = a4;
                *(float4*)&g_b[ob + (oc0-63)*NHW] = b4;
            }
        }
    }
}

__device__ __forceinline__ void fft_body(float* sm, int d, int n,
                                         const float* __restrict__ swr,
                                         const float* __restrict__ swi) {
    float *ar = sm, *ai = ar+64*RP, *br = ai+64*RP, *bi = br+64*RP;
    int tid = threadIdx.x;
    const float* pr0 = g_pad + ((size_t)(n*ND2 + d))*PLANEP;
    const float* pi0 = g_pad + ((size_t)(n*ND2 + 64 + d))*PLANEP;
    for (int l = tid; l < 4096; l += 256) {
        int hh = l>>6, ww = l&63;
        ar[hh*RP+ww] = pr0[(hh+1)*PADW + ww+1];
        ai[hh*RP+ww] = pi0[(hh+1)*PADW + ww+1];
    }
    __syncthreads();
    int r0 = (tid>>4)*4, c0 = (tid&15)*4;
    { // pass1: b[h][v] = sum_w a[h][w] F[v][w]
        u64 pr_[4][2] = {}, pi_[4][2] = {};
        for (int w = 0; w < 64; w++) {
            u64 g0 = ldg2(&g_twr[w*64+c0]),  g1 = ldg2(&g_twr[w*64+c0+2]);
            u64 q0 = ldg2(&g_twi[w*64+c0]),  q1 = ldg2(&g_twi[w*64+c0+2]);
            u64 n0 = ldg2(&g_twin[w*64+c0]), n1 = ldg2(&g_twin[w*64+c0+2]);
            #pragma unroll
            for (int i = 0; i < 4; i++) {
                float xr1 = ar[(r0+i)*RP+w], xi1 = ai[(r0+i)*RP+w];
                u64 bxr = bc(xr1), bxi = bc(xi1);
                fma2(pr_[i][0], bxr, g0); fma2(pr_[i][0], bxi, n0);
                fma2(pr_[i][1], bxr, g1); fma2(pr_[i][1], bxi, n1);
                fma2(pi_[i][0], bxr, q0); fma2(pi_[i][0], bxi, g0);
                fma2(pi_[i][1], bxr, q1); fma2(pi_[i][1], bxi, g1);
            }
        }
        #pragma unroll
        for (int i = 0; i < 4; i++) {
            *(float2*)&br[(r0+i)*RP+c0]   = up(pr_[i][0]);
            *(float2*)&br[(r0+i)*RP+c0+2] = up(pr_[i][1]);
            *(float2*)&bi[(r0+i)*RP+c0]   = up(pi_[i][0]);
            *(float2*)&bi[(r0+i)*RP+c0+2] = up(pi_[i][1]);
        }
    }
    __syncthreads();
    { // pass2: a[u][v] = sum_h F[u][h] b[h][v]
        u64 pr_[4][2] = {}, pi_[4][2] = {};
        for (int hs = 0; hs < 64; hs++) {
            u64 x0 = lds2(&br[hs*RP+c0]), x1 = lds2(&br[hs*RP+c0+2]);
            u64 y0 = lds2(&bi[hs*RP+c0]), y1 = lds2(&bi[hs*RP+c0+2]);
            float2 ga = *(const float2*)&g_twr[hs*64+r0],  gb2 = *(const float2*)&g_twr[hs*64+r0+2];
            float2 qa = *(const float2*)&g_twi[hs*64+r0],  qb = *(const float2*)&g_twi[hs*64+r0+2];
            float2 na = *(const float2*)&g_twin[hs*64+r0], nb = *(const float2*)&g_twin[hs*64+r0+2];
            float grs[4] = {ga.x, ga.y, gb2.x, gb2.y};
            float gis[4] = {qa.x, qa.y, qb.x, qb.y};
            float gns[4] = {na.x, na.y, nb.x, nb.y};
            #pragma unroll
            for (int i = 0; i < 4; i++) {
                u64 bgr = bc(grs[i]), bgi = bc(gis[i]), bgn = bc(gns[i]);
                fma2(pr_[i][0], bgr, x0); fma2(pr_[i][0], bgn, y0);
                fma2(pr_[i][1], bgr, x1); fma2(pr_[i][1], bgn, y1);
                fma2(pi_[i][0], bgr, y0); fma2(pi_[i][0], bgi, x0);
                fma2(pi_[i][1], bgr, y1); fma2(pi_[i][1], bgi, x1);
            }
        }
        __syncthreads();
        #pragma unroll
        for (int i = 0; i < 4; i++) {
            *(float2*)&ar[(r0+i)*RP+c0]   = up(pr_[i][0]);
            *(float2*)&ar[(r0+i)*RP+c0+2] = up(pr_[i][1]);
            *(float2*)&ai[(r0+i)*RP+c0]   = up(pi_[i][0]);
            *(float2*)&ai[(r0+i)*RP+c0+2] = up(pi_[i][1]);
        }
    }
    __syncthreads();
    { // pointwise * spec_w[d]
        const float* wr2 = swr + d*NHW; const float* wi2 = swi + d*NHW;
        for (int l = tid; l < 4096; l += 256) {
            int u = l>>6, v = l&63;
            float zr = ar[u*RP+v], zi = ai[u*RP+v];
            float wr_ = wr2[l], wi_ = wi2[l];
            ar[u*RP+v] = zr*wr_ - zi*wi_;
            ai[u*RP+v] = zr*wi_ + zi*wr_;
        }
    }
    __syncthreads();
    { // pass3: b[h][v] = sum_u conj(F)[h][u] a[u][v]  (conj: +sin on pr, -sin on pi)
        u64 pr_[4][2] = {}, pi_[4][2] = {};
        for (int us = 0; us < 64; us++) {
            u64 x0 = lds2(&ar[us*RP+c0]), x1 = lds2(&ar[us*RP+c0+2]);
            u64 y0 = lds2(&ai[us*RP+c0]), y1 = lds2(&ai[us*RP+c0+2]);
            float2 ga = *(const float2*)&g_twr[us*64+r0],  gb2 = *(const float2*)&g_twr[us*64+r0+2];
            float2 qa = *(const float2*)&g_twi[us*64+r0],  qb = *(const float2*)&g_twi[us*64+r0+2];
            float2 na = *(const float2*)&g_twin[us*64+r0], nb = *(const float2*)&g_twin[us*64+r0+2];
            float grs[4] = {ga.x, ga.y, gb2.x, gb2.y};
            float gis[4] = {qa.x, qa.y, qb.x, qb.y};
            float gns[4] = {na.x, na.y, nb.x, nb.y};
            #pragma unroll
            for (int i = 0; i < 4; i++) {
                u64 bgr = bc(grs[i]), bgi = bc(gis[i]), bgn = bc(gns[i]);
                fma2(pr_[i][0], bgr, x0); fma2(pr_[i][0], bgi, y0);
                fma2(pr_[i][1], bgr, x1); fma2(pr_[i][1], bgi, y1);
                fma2(pi_[i][0], bgr, y0); fma2(pi_[i][0], bgn, x0);
                fma2(pi_[i][1], bgr, y1); fma2(pi_[i][1], bgn, x1);
            }
        }
        #pragma unroll
        for (int i = 0; i < 4; i++) {
            *(float2*)&br[(r0+i)*RP+c0]   = up(pr_[i][0]);
            *(float2*)&br[(r0+i)*RP+c0+2] = up(pr_[i][1]);
            *(float2*)&bi[(r0+i)*RP+c0]   = up(pi_[i][0]);
            *(float2*)&bi[(r0+i)*RP+c0+2] = up(pi_[i][1]);
        }
    }
    __syncthreads();
    { // pass4: out[h][w] = (1/4096) sum_v b[h][v] conj(F)[w][v] -> spec into g_c/g_d
        u64 pr_[4][2] = {}, pi_[4][2] = {};
        for (int vs = 0; vs < 64; vs++) {
            u64 g0 = ldg2(&g_twr[vs*64+c0]),  g1 = ldg2(&g_twr[vs*64+c0+2]);
            u64 q0 = ldg2(&g_twi[vs*64+c0]),  q1 = ldg2(&g_twi[vs*64+c0+2]);
            u64 n0 = ldg2(&g_twin[vs*64+c0]), n1 = ldg2(&g_twin[vs*64+c0+2]);
            #pragma unroll
            for (int i = 0; i < 4; i++) {
                float xr1 = br[(r0+i)*RP+vs], xi1 = bi[(r0+i)*RP+vs];
                u64 bxr = bc(xr1), bxi = bc(xi1);
                fma2(pr_[i][0], bxr, g0); fma2(pr_[i][0], bxi, q0);
                fma2(pr_[i][1], bxr, g1); fma2(pr_[i][1], bxi, q1);
                fma2(pi_[i][0], bxi, g0); fma2(pi_[i][0], bxr, n0);
                fma2(pi_[i][1], bxi, g1); fma2(pi_[i][1], bxr, n1);
            }
        }
        const float sc = 1.f/4096.f;
        int base = n*ND*NHW + d*NHW;
        #pragma unroll
        for (int i = 0; i < 4; i++)
            for (int jp = 0; jp < 2; jp++) {
                int idx = base + (r0+i)*64 + c0 + 2*jp;
                float2 sr = up(pr_[i][jp]);
                float2 si = up(pi_[i][jp]);
                sr.x *= sc; sr.y *= sc; si.x *= sc; si.y *= sc;
                *(float2*)&g_c[idx] = sr;
                *(float2*)&g_d[idx] = si;
            }
    }
}

__global__ __launch_bounds__(256, 2) void k_convfft(const float* __restrict__ cb,
                                                    const float* __restrict__ swr,
                                                    const float* __restrict__ swi) {
    extern __shared__ float sm[];
    int bid = blockIdx.x;
    int grp = bid / 3, rem = bid - grp*3;
    if (rem == 0) {
        conv_body(sm, grp & 31, grp >> 5, cb);       // grp 0..2047 -> (hb, n)
    } else {
        int f = grp*2 + (rem - 1);                   // f 0..4095
        fft_body(sm, f & 63, f >> 6, swr, swi);
    }
}

// ---------- combine: x1 = g*cliff + (1-g)*spec + x_in -> g_a/g_b ----------
__global__ void k_comb(const float* __restrict__ xr, const float* __restrict__ xi,
                       const float* __restrict__ gate) {
    int i = (blockIdx.x*blockDim.x + threadIdx.x) * 4;
    float g = gate[0], omg = 1.f - g;
    float4 a = *(float4*)&g_a[i];
    float4 c = *(float4*)&g_c[i];
    float4 x = *(const float4*)&xr[i];
    a.x = g*a.x + omg*c.x + x.x;  a.y = g*a.y + omg*c.y + x.y;
    a.z = g*a.z + omg*c.z + x.z;  a.w = g*a.w + omg*c.w + x.w;
    *(float4*)&g_a[i] = a;
    float4 b = *(float4*)&g_b[i];
    float4 d = *(float4*)&g_d[i];
    float4 y = *(const float4*)&xi[i];
    b.x = g*b.x + omg*d.x + y.x;  b.y = g*b.y + omg*d.y + y.y;
    b.z = g*b.z + omg*d.z + y.z;  b.w = g*b.w + omg*d.w + y.w;
    *(float4*)&g_b[i] = b;
}

// ---------- fused temporal branch: LN + encode + recurrence + decode + resid ----------
#define TEMP_SM (6*64*RP*4)
__global__ __launch_bounds__(256, 2) void k_temporal(
        const float* __restrict__ er, const float* __restrict__ ei,
        const float* __restrict__ dmr, const float* __restrict__ dmi,
        const float* __restrict__ gam, const float* __restrict__ bet,
        const float* __restrict__ dt,  const float* __restrict__ lr_,
        const float* __restrict__ li_) {
    extern __shared__ float sm[];
    float *Er = sm, *Ei = Er+64*RP, *Dr = Ei+64*RP, *Di = Dr+64*RP;
    float *Xr = Di+64*RP, *Xi = Xr+64*RP;
    __shared__ float ps[4][64], pq[4][64], mb[64], rb[64];
    int pt = blockIdx.x, b = blockIdx.y, tid = threadIdx.x, hw0 = pt*64;
    for (int l = tid; l < 4096; l += 256) {
        int r_ = l>>6, c_ = l&63;
        Er[r_*RP+c_] = er[l];  Ei[r_*RP+c_] = ei[l];
        Dr[r_*RP+c_] = dmr[l]; Di[r_*RP+c_] = dmi[l];
    }
    int e0 = (tid>>4)*4, p0 = (tid&15)*4;
    float ddr[4], ddi[4], ffr[4], ffi[4];
    float dtb = dt[b];
    #pragma unroll
    for (int i = 0; i < 4; i++) {
        float lr = lr_[e0+i], li = li_[e0+i];
        float ex = expf(lr*dtb);
        float sn, cs; sincosf(li*dtb, &sn, &cs);
        ddr[i] = ex*cs; ddi[i] = ex*sn;
        float nr = ddr[i]-1.f, ni = ddi[i];
        float den = 1.f/(lr*lr + li*li);
        ffr[i] = (nr*lr + ni*li)*den;
        ffi[i] = (ni*lr - nr*li)*den;
    }
    u64 hrp[4][2] = {}, hip[4][2] = {};
    int lnp = tid & 63;
    for (int t = 0; t < NTT; t++) {
        int n = b*NTT + t;
        __syncthreads();
        float sum = 0.f, sq = 0.f;
        for (int l = tid; l < 4096; l += 256) {
            int dd = l>>6, p = l&63;
            int gi_ = (n*ND+dd)*NHW + hw0 + p;
            float vr = g_a[gi_], vi = g_b[gi_];
            Xr[dd*RP+p] = vr; Xi[dd*RP+p] = vi;
            sum += vr + vi; sq += vr*vr + vi*vi;
        }
        ps[tid>>6][lnp] = sum; pq[tid>>6][lnp] = sq;
        __syncthreads();
        if (tid < 64) {
            float S = ps[0][tid]+ps[1][tid]+ps[2][tid]+ps[3][tid];
            float Q = pq[0][tid]+pq[1][tid]+pq[2][tid]+pq[3][tid];
            float m = S*(1.f/128.f);
            mb[tid] = m; rb[tid] = rsqrtf(Q*(1.f/128.f) - m*m + 1e-5f);
        }
        __syncthreads();
        {
            float m = mb[lnp], r = rb[lnp];
            for (int l = tid; l < 4096; l += 256) {
                int dd = l>>6, p = l&63;
                Xr[dd*RP+p] = (Xr[dd*RP+p] - m)*r*gam[dd]    + bet[dd];
                Xi[dd*RP+p] = (Xi[dd*RP+p] - m)*r*gam[dd+64] + bet[dd+64];
            }
        }
        __syncthreads();
        u64 pr_[4][2] = {}, pi_[4][2] = {};
        for (int dd = 0; dd < 64; dd++) {
            u64 x0 = lds2(&Xr[dd*RP+p0]), x1 = lds2(&Xr[dd*RP+p0+2]);
            u64 y0 = lds2(&Xi[dd*RP+p0]), y1 = lds2(&Xi[dd*RP+p0+2]);
            float2 ea = *(const float2*)&Er[dd*RP+e0], eb = *(const float2*)&Er[dd*RP+e0+2];
            float2 qa = *(const float2*)&Ei[dd*RP+e0], qb = *(const float2*)&Ei[dd*RP+e0+2];
            float ers[4] = {ea.x, ea.y, eb.x, eb.y};
            float eis[4] = {qa.x, qa.y, qb.x, qb.y};
            #pragma unroll
            for (int i = 0; i < 4; i++) {
                u64 ber = bc(ers[i]), bei = bc(eis[i]), bnei = bc(-eis[i]);
                fma2(pr_[i][0], x0, ber); fma2(pr_[i][0], y0, bnei);
                fma2(pr_[i][1], x1, ber); fma2(pr_[i][1], y1, bnei);
                fma2(pi_[i][0], x0, bei); fma2(pi_[i][0], y0, ber);
                fma2(pi_[i][1], x1, bei); fma2(pi_[i][1], y1, ber);
            }
        }
        #pragma unroll
        for (int i = 0; i < 4; i++) {
            u64 bdr = bc(ddr[i]), bdi = bc(ddi[i]), bndi = bc(-ddi[i]);
            u64 bfr = bc(ffr[i]), bfi = bc(ffi[i]), bnfi = bc(-ffi[i]);
            #pragma unroll
            for (int jp = 0; jp < 2; jp++) {
                u64 nr_ = 0ull, ni_ = 0ull;
                fma2(nr_, hrp[i][jp], bdr); fma2(nr_, hip[i][jp], bndi);
                fma2(nr_, pr_[i][jp], bfr); fma2(nr_, pi_[i][jp], bnfi);
                fma2(ni_, hrp[i][jp], bdi); fma2(ni_, hip[i][jp], bdr);
                fma2(ni_, pr_[i][jp], bfi); fma2(ni_, pi_[i][jp], bfr);
                hrp[i][jp] = nr_; hip[i][jp] = ni_;
            }
        }
        __syncthreads();
        #pragma unroll
        for (int i = 0; i < 4; i++)
            for (int jp = 0; jp < 2; jp++) {
                *(float2*)&Xr[(e0+i)*RP + p0 + 2*jp] = up(hrp[i][jp]);
                *(float2*)&Xi[(e0+i)*RP + p0 + 2*jp] = up(hip[i][jp]);
            }
        __syncthreads();
        u64 acc[4][2] = {};
        for (int e = 0; e < 64; e++) {
            u64 x0 = lds2(&Xr[e*RP+p0]), x1 = lds2(&Xr[e*RP+p0+2]);
            u64 y0 = lds2(&Xi[e*RP+p0]), y1 = lds2(&Xi[e*RP+p0+2]);
            float2 da = *(const float2*)&Dr[e*RP+e0], db = *(const float2*)&Dr[e*RP+e0+2];
            float2 qa = *(const float2*)&Di[e*RP+e0], qb = *(const float2*)&Di[e*RP+e0+2];
            float drs[4] = {da.x, da.y, db.x, db.y};
            float dis[4] = {qa.x, qa.y, qb.x, qb.y};
            #pragma unroll
            for (int i = 0; i < 4; i++) {
                u64 bdr = bc(drs[i]), bnd = bc(-dis[i]);
                fma2(acc[i][0], x0, bdr); fma2(acc[i][0], y0, bnd);
                fma2(acc[i][1], x1, bdr); fma2(acc[i][1], y1, bnd);
            }
        }
        #pragma unroll
        for (int i = 0; i < 4; i++)
            for (int jp = 0; jp < 2; jp++) {
                int gi_ = (n*ND + e0+i)*NHW + hw0 + p0 + 2*jp;
                float2 v = up(acc[i][jp]);
                float2 rs = *(const float2*)&g_a[gi_];
                v.x += rs.x; v.y += rs.y;
                *(float2*)&g_c[gi_] = v;
            }
    }
}

// ---------- fast gelu ----------
__device__ __forceinline__ float gelu_f(float x) {
    float u = 0.7978845608028654f*(x + 0.044715f*x*x*x);
    return x * (1.f - __fdividef(1.f, __expf(2.f*u) + 1.f));
}

// ---------- fused MLP 128 -> 512(gelu) -> 128 + residual, f chunked by 64 ----------
#define MLP_SM ((128*68 + 64*68 + 8704)*4)
__global__ __launch_bounds__(256) void k_mlp(const float* __restrict__ w1,
                                             const float* __restrict__ b1,
                                             const float* __restrict__ w2,
                                             const float* __restrict__ b2,
                                             float* __restrict__ out) {
    extern __shared__ float sm[];
    float *Xs = sm;                // [128][68]
    float *Hs = Xs + 128*68;       // [64][68]
    float *Ws = Hs + 64*68;        // w1 chunk [128][68] or w2 chunk [64][132]
    int pt = blockIdx.x, n = blockIdx.y, tid = threadIdx.x, hw0 = pt*64;
    for (int l = tid; l < 128*64; l += 256) {
        int c = l>>6, p = l&63;
        float v = (c < 64) ? g_c[(n*ND+c)*NHW + hw0 + p]
                           : g_b[(n*ND+c-64)*NHW + hw0 + p];
        Xs[c*68+p] = v;
    }
    int fg = (tid>>4)*4, p0 = (tid&15)*4;
    int c8 = (tid>>4)*8;
    u64 accp[4][4];
    #pragma unroll
    for (int i = 0; i < 4; i++)
        for (int j = 0; j < 4; j++) accp[i][j] = 0ull;
    for (int fc = 0; fc < 8; fc++) {
        __syncthreads();
        for (int l = tid; l < 128*64; l += 256) {
            int c = l>>6, f = l&63;
            Ws[c*68+f] = w1[c*512 + fc*64 + f];
        }
        __syncthreads();
        u64 a2p[2][4];
        #pragma unroll
        for (int i = 0; i < 2; i++)
            for (int j = 0; j < 4; j++) a2p[i][j] = 0ull;
        for (int c = 0; c < 128; c++) {
            float4 xq = *(const float4*)&Xs[c*68+p0];
            u64 bx[4] = {bc(xq.x), bc(xq.y), bc(xq.z), bc(xq.w)};
            u64 w01 = lds2(&Ws[c*68+fg]), w23 = lds2(&Ws[c*68+fg+2]);
            fma2(a2p[0][0], w01, bx[0]); fma2(a2p[0][1], w01, bx[1]);
            fma2(a2p[0][2], w01, bx[2]); fma2(a2p[0][3], w01, bx[3]);
            fma2(a2p[1][0], w23, bx[0]); fma2(a2p[1][1], w23, bx[1]);
            fma2(a2p[1][2], w23, bx[2]); fma2(a2p[1][3], w23, bx[3]);
        }
        __syncthreads();
        #pragma unroll
        for (int ip = 0; ip < 2; ip++) {
            int fA = fg + 2*ip, fB = fA + 1;
            float biasA = b1[fc*64 + fA], biasB = b1[fc*64 + fB];
            float2 v0 = up(a2p[ip][0]), v1 = up(a2p[ip][1]);
            float2 v2 = up(a2p[ip][2]), v3 = up(a2p[ip][3]);
            float4 hA = make_float4(gelu_f(v0.x + biasA), gelu_f(v1.x + biasA),
                                    gelu_f(v2.x + biasA), gelu_f(v3.x + biasA));
            float4 hB = make_float4(gelu_f(v0.y + biasB), gelu_f(v1.y + biasB),
                                    gelu_f(v2.y + biasB), gelu_f(v3.y + biasB));
            *(float4*)&Hs[fA*68 + p0] = hA;
            *(float4*)&Hs[fB*68 + p0] = hB;
        }
        for (int l = tid; l < 64*128; l += 256) {
            int f = l>>7, c = l&127;
            Ws[f*132+c] = w2[(fc*64+f)*128 + c];
        }
        __syncthreads();
        for (int f = 0; f < 64; f++) {
            float4 hq = *(const float4*)&Hs[f*68+p0];
            u64 bh[4] = {bc(hq.x), bc(hq.y), bc(hq.z), bc(hq.w)};
            const u64* wp = (const u64*)&Ws[f*132+c8];
            #pragma unroll
            for (int ip = 0; ip < 4; ip++) {
                u64 wv = wp[ip];
                fma2(accp[ip][0], wv, bh[0]); fma2(accp[ip][1], wv, bh[1]);
                fma2(accp[ip][2], wv, bh[2]); fma2(accp[ip][3], wv, bh[3]);
            }
        }
    }
    #pragma unroll
    for (int ip = 0; ip < 4; ip++) {
        int cA = c8 + 2*ip, cB = cA + 1;
        float bA = b2[cA], bB = b2[cB];
        #pragma unroll
        for (int j = 0; j < 4; j++) {
            float2 v = up(accp[ip][j]);
            int p = p0 + j;
            float resA = (cA < 64) ? g_c[(n*ND+cA)*NHW + hw0 + p]
                                   : g_b[(n*ND+cA-64)*NHW + hw0 + p];
            float resB = (cB < 64) ? g_c[(n*ND+cB)*NHW + hw0 + p]
                                   : g_b[(n*ND+cB-64)*NHW + hw0 + p];
            out[((size_t)n*ND2 + cA)*NHW + hw0 + p] = v.x + bA + resA;
            out[((size_t)n*ND2 + cB)*NHW + hw0 + p] = v.y + bB + resB;
        }
    }
}

extern "C" void kernel_launch(void* const* d_in, const int* in_sizes, int n_in,
                              void* d_out, int out_size) {
    const float* xr   = (const float*)d_in[0];
    const float* xi   = (const float*)d_in[1];
    const float* dt   = (const float*)d_in[2];
    const float* lsg  = (const float*)d_in[3];
    const float* lsb  = (const float*)d_in[4];
    const float* cw   = (const float*)d_in[5];
    const float* cb   = (const float*)d_in[6];
    const float* swr  = (const float*)d_in[7];
    const float* swi  = (const float*)d_in[8];
    const float* gate = (const float*)d_in[9];
    const float* ltg  = (const float*)d_in[10];
    const float* ltb  = (const float*)d_in[11];
    const float* lamr = (const float*)d_in[12];
    const float* lami = (const float*)d_in[13];
    const float* enr  = (const float*)d_in[14];
    const float* eni  = (const float*)d_in[15];
    const float* dcr  = (const float*)d_in[16];
    const float* dci  = (const float*)d_in[17];
    const float* w1   = (const float*)d_in[18];
    const float* b1   = (const float*)d_in[19];
    const float* w2   = (const float*)d_in[20];
    const float* b2   = (const float*)d_in[21];
    float* out = (float*)d_out;

    cudaFuncSetAttribute(k_convfft,  cudaFuncAttributeMaxDynamicSharedMemorySize, CF_SM);
    cudaFuncSetAttribute(k_temporal, cudaFuncAttributeMaxDynamicSharedMemorySize, TEMP_SM);
    cudaFuncSetAttribute(k_mlp,      cudaFuncAttributeMaxDynamicSharedMemorySize, MLP_SM);

    dim3 gHN(64, 64);
    k_init<<<(128*128*9 + 255)/256, 256>>>(cw);
    k_ln0<<<gHN, dim3(64,4)>>>(xr, xi, lsg, lsb);
    k_convfft<<<6144, 256, CF_SM>>>(cb, swr, swi);
    k_comb<<<NTOT/1024, 256>>>(xr, xi, gate);
    k_temporal<<<dim3(64, NBB), 256, TEMP_SM>>>(enr, eni, dcr, dci, ltg, ltb, dt, lamr, lami);
    k_mlp<<<gHN, 256, MLP_SM>>>(w1, b1, w2, b2, out);
}

// round 14
// speedup vs baseline: 1.1545x; 1.0913x over previous
#include <cuda_runtime.h>
#include <math.h>

#define ND 64
#define ND2 128
#define NHW 4096
#define NBT 64
#define NTT 16
#define NBB 4
#define NTOT (NBT*ND*NHW)
#define PADW 66
#define PLANEP (PADW*PADW)
#define RP 66

typedef unsigned long long u64;

__device__ float g_pad[(size_t)NBT*ND2*PLANEP];   // zero-init: borders stay 0 forever
__device__ float g_a[NTOT], g_b[NTOT], g_c[NTOT], g_d[NTOT];
__device__ float g_w[128*128*9];                  // conv weights transposed [ic*9+tap][oc]
__device__ float g_twr[4096], g_twi[4096], g_twin[4096];  // DFT twiddles: cos, sin, -sin

// ---- f32x2 helpers ----
__device__ __forceinline__ u64 pk(float lo, float hi) {
    u64 r; asm("mov.b64 %0, {%1,%2};" : "=l"(r) : "f"(lo), "f"(hi)); return r;
}
__device__ __forceinline__ u64 bc(float v) { return pk(v, v); }
__device__ __forceinline__ void fma2(u64& d, u64 a, u64 b) {
    asm("fma.rn.f32x2 %0, %1, %2, %0;" : "+l"(d) : "l"(a), "l"(b));
}
__device__ __forceinline__ float2 up(u64 v) {
    float2 f; asm("mov.b64 {%0,%1}, %2;" : "=f"(f.x), "=f"(f.y) : "l"(v)); return f;
}
__device__ __forceinline__ u64 lds2(const float* p) { return *(const u64*)p; }
__device__ __forceinline__ u64 ldg2(const float* p) { return *(const u64*)p; }

// ---------- init ----------
__global__ void k_init(const float* __restrict__ cw) {
    int i = blockIdx.x*blockDim.x + threadIdx.x;
    if (i < 4096) {
        const float W64 = 6.28318530717958647692f/64.f;
        int u = i>>6, w = i&63, t = (u*w)&63;
        float sv, cv; sincosf(-W64*(float)t, &sv, &cv);
        g_twr[i] = cv; g_twi[i] = sv; g_twin[i] = -sv;
    }
    if (i < 128*128*9) {
        int oc = i / 1152, rem = i - oc*1152;
        g_w[rem*128 + oc] = cw[i];
    }
}

// ---------- spatial complex LayerNorm -> padded buffer ----------
__global__ void k_ln0(const float* __restrict__ xr, const float* __restrict__ xi,
                      const float* __restrict__ gam, const float* __restrict__ bet) {
    __shared__ float s[128][64];
    __shared__ float ps[4][64], pq[4][64], mb[64], rb[64];
    int h = blockIdx.x, n = blockIdx.y;
    int tx = threadIdx.x, ty = threadIdx.y;
    int base = n*(ND*NHW) + h*64 + tx;
    float sum = 0.f, sq = 0.f;
    for (int j = 0; j < 32; j++) {
        int c = ty*32 + j;
        float v = (c < 64) ? xr[base + c*NHW] : xi[base + (c-64)*NHW];
        s[c][tx] = v; sum += v; sq += v*v;
    }
    ps[ty][tx] = sum; pq[ty][tx] = sq;
    __syncthreads();
    if (ty == 0) {
        float S = ps[0][tx]+ps[1][tx]+ps[2][tx]+ps[3][tx];
        float Q = pq[0][tx]+pq[1][tx]+pq[2][tx]+pq[3][tx];
        float m = S*(1.f/128.f);
        mb[tx] = m; rb[tx] = rsqrtf(Q*(1.f/128.f) - m*m + 1e-5f);
    }
    __syncthreads();
    float m = mb[tx], r = rb[tx];
    for (int j = 0; j < 32; j++) {
        int c = ty*32 + j;
        float y = (s[c][tx] - m)*r*gam[c] + bet[c];
        g_pad[((size_t)(n*ND2 + c))*PLANEP + (h+1)*PADW + tx+1] = y;
    }
}

// ---------- merged conv(2 rows/block) + fft ----------
#define CF_SM ((4*16*68 + 16*9*128)*4)

__device__ __forceinline__ void conv_body(float* sm, int hb, int n,
                                          const float* __restrict__ cb) {
    float* sin_ = sm;              // [4][16][68]  rows h0..h0+3 per ic chunk
    float* sw   = sm + 4*16*68;    // [16*9][128]
    int tid = threadIdx.x;
    int h0 = hb*2;
    const float* src = g_pad + (size_t)n*ND2*PLANEP;
    int wg = tid & 15, og = tid >> 4, w0 = wg*4;
    u64 accp[2][4][4];
    #pragma unroll
    for (int hh = 0; hh < 2; hh++)
        for (int a = 0; a < 4; a++)
            for (int b2 = 0; b2 < 4; b2++) accp[hh][a][b2] = 0ull;
    for (int icc = 0; icc < 8; icc++) {
        __syncthreads();
        for (int l = tid; l < 4*16*68; l += 256) {
            int r = l/(16*68), rem = l - r*(16*68);
            int icl = rem/68, c = rem - icl*68;
            sin_[l] = (c < 66) ? src[(size_t)(icc*16+icl)*PLANEP + (h0 + r)*PADW + c] : 0.f;
        }
        {   // 128-bit weight staging: both sides fully contiguous
            const float4* wsrc = (const float4*)(g_w + icc*16*9*128);
            float4* wdst = (float4*)sw;
            for (int l = tid; l < 16*9*128/4; l += 256)
                wdst[l] = wsrc[l];
        }
        __syncthreads();
        #pragma unroll 1
        for (int icl = 0; icl < 16; icl++) {
            float inv[4][6];
            #pragma unroll
            for (int r = 0; r < 4; r++) {
                const float* rp = &sin_[(r*16+icl)*68 + w0];
                float4 q = *(const float4*)rp;
                float2 t = *(const float2*)(rp+4);
                inv[r][0]=q.x; inv[r][1]=q.y; inv[r][2]=q.z;
                inv[r][3]=q.w; inv[r][4]=t.x; inv[r][5]=t.y;
            }
            #pragma unroll
            for (int ky = 0; ky < 3; ky++)
                for (int kx = 0; kx < 3; kx++) {
                    int tap = ky*3 + kx;
                    const u64* wp = (const u64*)&sw[(icl*9+tap)*128 + og*8];
                    u64 wv0 = wp[0], wv1 = wp[1], wv2 = wp[2], wv3 = wp[3];
                    #pragma unroll
                    for (int hh = 0; hh < 2; hh++) {
                        u64 b0 = bc(inv[ky+hh][kx]),   b1 = bc(inv[ky+hh][kx+1]);
                        u64 b2 = bc(inv[ky+hh][kx+2]), b3 = bc(inv[ky+hh][kx+3]);
                        fma2(accp[hh][0][0], wv0, b0); fma2(accp[hh][0][1], wv0, b1);
                        fma2(accp[hh][0][2], wv0, b2); fma2(accp[hh][0][3], wv0, b3);
                        fma2(accp[hh][1][0], wv1, b0); fma2(accp[hh][1][1], wv1, b1);
                        fma2(accp[hh][1][2], wv1, b2); fma2(accp[hh][1][3], wv1, b3);
                        fma2(accp[hh][2][0], wv2, b0); fma2(accp[hh][2][1], wv2, b1);
                        fma2(accp[hh][2][2], wv2, b2); fma2(accp[hh][2][3], wv2, b3);
                        fma2(accp[hh][3][0], wv3, b0); fma2(accp[hh][3][1], wv3, b1);
                        fma2(accp[hh][3][2], wv3, b2); fma2(accp[hh][3][3], wv3, b3);
                    }
                }
        }
    }
    #pragma unroll
    for (int hh = 0; hh < 2; hh++) {
        int ob = n*(ND*NHW) + (h0+hh)*64 + w0;
        #pragma unroll
        for (int op = 0; op < 4; op++) {
            int oc0 = og*8 + 2*op;
            float bia0 = cb[oc0], bia1 = cb[oc0+1];
            float2 v0 = up(accp[hh][op][0]), v1 = up(accp[hh][op][1]);
            float2 v2 = up(accp[hh][op][2]), v3 = up(accp[hh][op][3]);
            float4 a4 = make_float4(v0.x+bia0, v1.x+bia0, v2.x+bia0, v3.x+bia0);
            float4 b4 = make_float4(v0.y+bia1, v1.y+bia1, v2.y+bia1, v3.y+bia1);
            if (oc0 < 64) {
                *(float4*)&g_a[ob + oc0*NHW]     = a4;
                *(float4*)&g_a[ob + (oc0+1)*NHW] = b4;
            } else {
                *(float4*)&g_b[ob + (oc0-64)*NHW] = a4;
                *(float4*)&g_b[ob + (oc0-63)*NHW] = b4;
            }
        }
    }
}

__device__ __forceinline__ void fft_body(float* sm, int d, int n,
                                         const float* __restrict__ swr,
                                         const float* __restrict__ swi) {
    float *ar = sm, *ai = ar+64*RP, *br = ai+64*RP, *bi = br+64*RP;
    int tid = threadIdx.x;
    const float* pr0 = g_pad + ((size_t)(n*ND2 + d))*PLANEP;
    const float* pi0 = g_pad + ((size_t)(n*ND2 + 64 + d))*PLANEP;
    for (int l = tid; l < 4096; l += 256) {
        int hh = l>>6, ww = l&63;
        ar[hh*RP+ww] = pr0[(hh+1)*PADW + ww+1];
        ai[hh*RP+ww] = pi0[(hh+1)*PADW + ww+1];
    }
    __syncthreads();
    int r0 = (tid>>4)*4, c0 = (tid&15)*4;
    { // pass1
        u64 pr_[4][2] = {}, pi_[4][2] = {};
        for (int w = 0; w < 64; w++) {
            u64 g0 = ldg2(&g_twr[w*64+c0]),  g1 = ldg2(&g_twr[w*64+c0+2]);
            u64 q0 = ldg2(&g_twi[w*64+c0]),  q1 = ldg2(&g_twi[w*64+c0+2]);
            u64 n0 = ldg2(&g_twin[w*64+c0]), n1 = ldg2(&g_twin[w*64+c0+2]);
            #pragma unroll
            for (int i = 0; i < 4; i++) {
                float xr1 = ar[(r0+i)*RP+w], xi1 = ai[(r0+i)*RP+w];
                u64 bxr = bc(xr1), bxi = bc(xi1);
                fma2(pr_[i][0], bxr, g0); fma2(pr_[i][0], bxi, n0);
                fma2(pr_[i][1], bxr, g1); fma2(pr_[i][1], bxi, n1);
                fma2(pi_[i][0], bxr, q0); fma2(pi_[i][0], bxi, g0);
                fma2(pi_[i][1], bxr, q1); fma2(pi_[i][1], bxi, g1);
            }
        }
        #pragma unroll
        for (int i = 0; i < 4; i++) {
            *(float2*)&br[(r0+i)*RP+c0]   = up(pr_[i][0]);
            *(float2*)&br[(r0+i)*RP+c0+2] = up(pr_[i][1]);
            *(float2*)&bi[(r0+i)*RP+c0]   = up(pi_[i][0]);
            *(float2*)&bi[(r0+i)*RP+c0+2] = up(pi_[i][1]);
        }
    }
    __syncthreads();
    { // pass2
        u64 pr_[4][2] = {}, pi_[4][2] = {};
        for (int hs = 0; hs < 64; hs++) {
            u64 x0 = lds2(&br[hs*RP+c0]), x1 = lds2(&br[hs*RP+c0+2]);
            u64 y0 = lds2(&bi[hs*RP+c0]), y1 = lds2(&bi[hs*RP+c0+2]);
            float2 ga = *(const float2*)&g_twr[hs*64+r0],  gb2 = *(const float2*)&g_twr[hs*64+r0+2];
            float2 qa = *(const float2*)&g_twi[hs*64+r0],  qb = *(const float2*)&g_twi[hs*64+r0+2];
            float2 na = *(const float2*)&g_twin[hs*64+r0], nb = *(const float2*)&g_twin[hs*64+r0+2];
            float grs[4] = {ga.x, ga.y, gb2.x, gb2.y};
            float gis[4] = {qa.x, qa.y, qb.x, qb.y};
            float gns[4] = {na.x, na.y, nb.x, nb.y};
            #pragma unroll
            for (int i = 0; i < 4; i++) {
                u64 bgr = bc(grs[i]), bgi = bc(gis[i]), bgn = bc(gns[i]);
                fma2(pr_[i][0], bgr, x0); fma2(pr_[i][0], bgn, y0);
                fma2(pr_[i][1], bgr, x1); fma2(pr_[i][1], bgn, y1);
                fma2(pi_[i][0], bgr, y0); fma2(pi_[i][0], bgi, x0);
                fma2(pi_[i][1], bgr, y1); fma2(pi_[i][1], bgi, x1);
            }
        }
        __syncthreads();
        #pragma unroll
        for (int i = 0; i < 4; i++) {
            *(float2*)&ar[(r0+i)*RP+c0]   = up(pr_[i][0]);
            *(float2*)&ar[(r0+i)*RP+c0+2] = up(pr_[i][1]);
            *(float2*)&ai[(r0+i)*RP+c0]   = up(pi_[i][0]);
            *(float2*)&ai[(r0+i)*RP+c0+2] = up(pi_[i][1]);
        }
    }
    __syncthreads();
    { // pointwise * spec_w[d]
        const float* wr2 = swr + d*NHW; const float* wi2 = swi + d*NHW;
        for (int l = tid; l < 4096; l += 256) {
            int u = l>>6, v = l&63;
            float zr = ar[u*RP+v], zi = ai[u*RP+v];
            float wr_ = wr2[l], wi_ = wi2[l];
            ar[u*RP+v] = zr*wr_ - zi*wi_;
            ai[u*RP+v] = zr*wi_ + zi*wr_;
        }
    }
    __syncthreads();
    { // pass3 (conj: +sin on pr, -sin on pi)
        u64 pr_[4][2] = {}, pi_[4][2] = {};
        for (int us = 0; us < 64; us++) {
            u64 x0 = lds2(&ar[us*RP+c0]), x1 = lds2(&ar[us*RP+c0+2]);
            u64 y0 = lds2(&ai[us*RP+c0]), y1 = lds2(&ai[us*RP+c0+2]);
            float2 ga = *(const float2*)&g_twr[us*64+r0],  gb2 = *(const float2*)&g_twr[us*64+r0+2];
            float2 qa = *(const float2*)&g_twi[us*64+r0],  qb = *(const float2*)&g_twi[us*64+r0+2];
            float2 na = *(const float2*)&g_twin[us*64+r0], nb = *(const float2*)&g_twin[us*64+r0+2];
            float grs[4] = {ga.x, ga.y, gb2.x, gb2.y};
            float gis[4] = {qa.x, qa.y, qb.x, qb.y};
            float gns[4] = {na.x, na.y, nb.x, nb.y};
            #pragma unroll
            for (int i = 0; i < 4; i++) {
                u64 bgr = bc(grs[i]), bgi = bc(gis[i]), bgn = bc(gns[i]);
                fma2(pr_[i][0], bgr, x0); fma2(pr_[i][0], bgi, y0);
                fma2(pr_[i][1], bgr, x1); fma2(pr_[i][1], bgi, y1);
                fma2(pi_[i][0], bgr, y0); fma2(pi_[i][0], bgn, x0);
                fma2(pi_[i][1], bgr, y1); fma2(pi_[i][1], bgn, x1);
            }
        }
        #pragma unroll
        for (int i = 0; i < 4; i++) {
            *(float2*)&br[(r0+i)*RP+c0]   = up(pr_[i][0]);
            *(float2*)&br[(r0+i)*RP+c0+2] = up(pr_[i][1]);
            *(float2*)&bi[(r0+i)*RP+c0]   = up(pi_[i][0]);
            *(float2*)&bi[(r0+i)*RP+c0+2] = up(pi_[i][1]);
        }
    }
    __syncthreads();
    { // pass4 -> spec (scaled) into g_c/g_d
        u64 pr_[4][2] = {}, pi_[4][2] = {};
        for (int vs = 0; vs < 64; vs++) {
            u64 g0 = ldg2(&g_twr[vs*64+c0]),  g1 = ldg2(&g_twr[vs*64+c0+2]);
            u64 q0 = ldg2(&g_twi[vs*64+c0]),  q1 = ldg2(&g_twi[vs*64+c0+2]);
            u64 n0 = ldg2(&g_twin[vs*64+c0]), n1 = ldg2(&g_twin[vs*64+c0+2]);
            #pragma unroll
            for (int i = 0; i < 4; i++) {
                float xr1 = br[(r0+i)*RP+vs], xi1 = bi[(r0+i)*RP+vs];
                u64 bxr = bc(xr1), bxi = bc(xi1);
                fma2(pr_[i][0], bxr, g0); fma2(pr_[i][0], bxi, q0);
                fma2(pr_[i][1], bxr, g1); fma2(pr_[i][1], bxi, q1);
                fma2(pi_[i][0], bxi, g0); fma2(pi_[i][0], bxr, n0);
                fma2(pi_[i][1], bxi, g1); fma2(pi_[i][1], bxr, n1);
            }
        }
        const float sc = 1.f/4096.f;
        int base = n*ND*NHW + d*NHW;
        #pragma unroll
        for (int i = 0; i < 4; i++)
            for (int jp = 0; jp < 2; jp++) {
                int idx = base + (r0+i)*64 + c0 + 2*jp;
                float2 sr = up(pr_[i][jp]);
                float2 si = up(pi_[i][jp]);
                sr.x *= sc; sr.y *= sc; si.x *= sc; si.y *= sc;
                *(float2*)&g_c[idx] = sr;
                *(float2*)&g_d[idx] = si;
            }
    }
}

__global__ __launch_bounds__(256, 2) void k_convfft(const float* __restrict__ cb,
                                                    const float* __restrict__ swr,
                                                    const float* __restrict__ swi) {
    extern __shared__ float sm[];
    int bid = blockIdx.x;
    int grp = bid / 3, rem = bid - grp*3;
    if (rem == 0) {
        conv_body(sm, grp & 31, grp >> 5, cb);       // grp 0..2047 -> (hb, n)
    } else {
        int f = grp*2 + (rem - 1);                   // f 0..4095
        fft_body(sm, f & 63, f >> 6, swr, swi);
    }
}

// ---------- combine: x1 = g*cliff + (1-g)*spec + x_in -> g_a/g_b ----------
__global__ void k_comb(const float* __restrict__ xr, const float* __restrict__ xi,
                       const float* __restrict__ gate) {
    int i = (blockIdx.x*blockDim.x + threadIdx.x) * 4;
    float g = gate[0], omg = 1.f - g;
    float4 a = *(float4*)&g_a[i];
    float4 c = *(float4*)&g_c[i];
    float4 x = *(const float4*)&xr[i];
    a.x = g*a.x + omg*c.x + x.x;  a.y = g*a.y + omg*c.y + x.y;
    a.z = g*a.z + omg*c.z + x.z;  a.w = g*a.w + omg*c.w + x.w;
    *(float4*)&g_a[i] = a;
    float4 b = *(float4*)&g_b[i];
    float4 d = *(float4*)&g_d[i];
    float4 y = *(const float4*)&xi[i];
    b.x = g*b.x + omg*d.x + y.x;  b.y = g*b.y + omg*d.y + y.y;
    b.z = g*b.z + omg*d.z + y.z;  b.w = g*b.w + omg*d.w + y.w;
    *(float4*)&g_b[i] = b;
}

// ---------- fused temporal branch: LN + encode + recurrence + decode + resid ----------
#define TEMP_SM (6*64*RP*4)
__global__ __launch_bounds__(256, 2) void k_temporal(
        const float* __restrict__ er, const float* __restrict__ ei,
        const float* __restrict__ dmr, const float* __restrict__ dmi,
        const float* __restrict__ gam, const float* __restrict__ bet,
        const float* __restrict__ dt,  const float* __restrict__ lr_,
        const float* __restrict__ li_) {
    extern __shared__ float sm[];
    float *Er = sm, *Ei = Er+64*RP, *Dr = Ei+64*RP, *Di = Dr+64*RP;
    float *Xr = Di+64*RP, *Xi = Xr+64*RP;
    __shared__ float ps[16][64], pq[16][64], mb[64], rb[64];
    int pt = blockIdx.x, b = blockIdx.y, tid = threadIdx.x, hw0 = pt*64;
    for (int l = tid; l < 4096; l += 256) {
        int r_ = l>>6, c_ = l&63;
        Er[r_*RP+c_] = er[l];  Ei[r_*RP+c_] = ei[l];
        Dr[r_*RP+c_] = dmr[l]; Di[r_*RP+c_] = dmi[l];
    }
    int e0 = (tid>>4)*4, p0 = (tid&15)*4;
    int gq = tid>>4, q = tid&15, p4 = q*4;
    float ddr[4], ddi[4], ffr[4], ffi[4];
    float dtb = dt[b];
    #pragma unroll
    for (int i = 0; i < 4; i++) {
        float lr = lr_[e0+i], li = li_[e0+i];
        float ex = expf(lr*dtb);
        float sn, cs; sincosf(li*dtb, &sn, &cs);
        ddr[i] = ex*cs; ddi[i] = ex*sn;
        float nr = ddr[i]-1.f, ni = ddi[i];
        float den = 1.f/(lr*lr + li*li);
        ffr[i] = (nr*lr + ni*li)*den;
        ffi[i] = (ni*lr - nr*li)*den;
    }
    u64 hrp[4][2] = {}, hip[4][2] = {};
    int lnp = tid & 63;
    for (int t = 0; t < NTT; t++) {
        int n = b*NTT + t;
        __syncthreads();
        // vectorized load: thread covers positions p4..p4+3, dd = gq + 16k
        float s4[4] = {0.f,0.f,0.f,0.f}, q4[4] = {0.f,0.f,0.f,0.f};
        #pragma unroll
        for (int k = 0; k < 4; k++) {
            int dd = gq + k*16;
            int gi_ = (n*ND+dd)*NHW + hw0 + p4;
            float4 vr = *(const float4*)&g_a[gi_];
            float4 vi = *(const float4*)&g_b[gi_];
            *(float2*)&Xr[dd*RP+p4]   = make_float2(vr.x, vr.y);
            *(float2*)&Xr[dd*RP+p4+2] = make_float2(vr.z, vr.w);
            *(float2*)&Xi[dd*RP+p4]   = make_float2(vi.x, vi.y);
            *(float2*)&Xi[dd*RP+p4+2] = make_float2(vi.z, vi.w);
            s4[0] += vr.x + vi.x; q4[0] += vr.x*vr.x + vi.x*vi.x;
            s4[1] += vr.y + vi.y; q4[1] += vr.y*vr.y + vi.y*vi.y;
            s4[2] += vr.z + vi.z; q4[2] += vr.z*vr.z + vi.z*vi.z;
            s4[3] += vr.w + vi.w; q4[3] += vr.w*vr.w + vi.w*vi.w;
        }
        #pragma unroll
        for (int j = 0; j < 4; j++) { ps[gq][p4+j] = s4[j]; pq[gq][p4+j] = q4[j]; }
        __syncthreads();
        if (tid < 64) {
            float S = 0.f, Q = 0.f;
            #pragma unroll
            for (int g2 = 0; g2 < 16; g2++) { S += ps[g2][tid]; Q += pq[g2][tid]; }
            float m = S*(1.f/128.f);
            mb[tid] = m; rb[tid] = rsqrtf(Q*(1.f/128.f) - m*m + 1e-5f);
        }
        __syncthreads();
        {
            float m = mb[lnp], r = rb[lnp];
            for (int l = tid; l < 4096; l += 256) {
                int dd = l>>6, p = l&63;
                Xr[dd*RP+p] = (Xr[dd*RP+p] - m)*r*gam[dd]    + bet[dd];
                Xi[dd*RP+p] = (Xi[dd*RP+p] - m)*r*gam[dd+64] + bet[dd+64];
            }
        }
        __syncthreads();
        u64 pr_[4][2] = {}, pi_[4][2] = {};
        for (int dd = 0; dd < 64; dd++) {
            u64 x0 = lds2(&Xr[dd*RP+p0]), x1 = lds2(&Xr[dd*RP+p0+2]);
            u64 y0 = lds2(&Xi[dd*RP+p0]), y1 = lds2(&Xi[dd*RP+p0+2]);
            float2 ea = *(const float2*)&Er[dd*RP+e0], eb = *(const float2*)&Er[dd*RP+e0+2];
            float2 qa = *(const float2*)&Ei[dd*RP+e0], qb = *(const float2*)&Ei[dd*RP+e0+2];
            float ers[4] = {ea.x, ea.y, eb.x, eb.y};
            float eis[4] = {qa.x, qa.y, qb.x, qb.y};
            #pragma unroll
            for (int i = 0; i < 4; i++) {
                u64 ber = bc(ers[i]), bei = bc(eis[i]), bnei = bc(-eis[i]);
                fma2(pr_[i][0], x0, ber); fma2(pr_[i][0], y0, bnei);
                fma2(pr_[i][1], x1, ber); fma2(pr_[i][1], y1, bnei);
                fma2(pi_[i][0], x0, bei); fma2(pi_[i][0], y0, ber);
                fma2(pi_[i][1], x1, bei); fma2(pi_[i][1], y1, ber);
            }
        }
        #pragma unroll
        for (int i = 0; i < 4; i++) {
            u64 bdr = bc(ddr[i]), bdi = bc(ddi[i]), bndi = bc(-ddi[i]);
            u64 bfr = bc(ffr[i]), bfi = bc(ffi[i]), bnfi = bc(-ffi[i]);
            #pragma unroll
            for (int jp = 0; jp < 2; jp++) {
                u64 nr_ = 0ull, ni_ = 0ull;
                fma2(nr_, hrp[i][jp], bdr); fma2(nr_, hip[i][jp], bndi);
                fma2(nr_, pr_[i][jp], bfr); fma2(nr_, pi_[i][jp], bnfi);
                fma2(ni_, hrp[i][jp], bdi); fma2(ni_, hip[i][jp], bdr);
                fma2(ni_, pr_[i][jp], bfi); fma2(ni_, pi_[i][jp], bfr);
                hrp[i][jp] = nr_; hip[i][jp] = ni_;
            }
        }
        __syncthreads();
        #pragma unroll
        for (int i = 0; i < 4; i++)
            for (int jp = 0; jp < 2; jp++) {
                *(float2*)&Xr[(e0+i)*RP + p0 + 2*jp] = up(hrp[i][jp]);
                *(float2*)&Xi[(e0+i)*RP + p0 + 2*jp] = up(hip[i][jp]);
            }
        __syncthreads();
        u64 acc[4][2] = {};
        for (int e = 0; e < 64; e++) {
            u64 x0 = lds2(&Xr[e*RP+p0]), x1 = lds2(&Xr[e*RP+p0+2]);
            u64 y0 = lds2(&Xi[e*RP+p0]), y1 = lds2(&Xi[e*RP+p0+2]);
            float2 da = *(const float2*)&Dr[e*RP+e0], db = *(const float2*)&Dr[e*RP+e0+2];
            float2 qa = *(const float2*)&Di[e*RP+e0], qb = *(const float2*)&Di[e*RP+e0+2];
            float drs[4] = {da.x, da.y, db.x, db.y};
            float dis[4] = {qa.x, qa.y, qb.x, qb.y};
            #pragma unroll
            for (int i = 0; i < 4; i++) {
                u64 bdr = bc(drs[i]), bnd = bc(-dis[i]);
                fma2(acc[i][0], x0, bdr); fma2(acc[i][0], y0, bnd);
                fma2(acc[i][1], x1, bdr); fma2(acc[i][1], y1, bnd);
            }
        }
        #pragma unroll
        for (int i = 0; i < 4; i++)
            for (int jp = 0; jp < 2; jp++) {
                int gi_ = (n*ND + e0+i)*NHW + hw0 + p0 + 2*jp;
                float2 v = up(acc[i][jp]);
                float2 rs = *(const float2*)&g_a[gi_];
                v.x += rs.x; v.y += rs.y;
                *(float2*)&g_c[gi_] = v;
            }
    }
}

// ---------- fast gelu ----------
__device__ __forceinline__ float gelu_f(float x) {
    float u = 0.7978845608028654f*(x + 0.044715f*x*x*x);
    return x * (1.f - __fdividef(1.f, __expf(2.f*u) + 1.f));
}

// ---------- fused MLP 128 -> 512(gelu) -> 128 + residual, f chunked by 64 ----------
#define MLP_SM ((128*68 + 64*68 + 8704)*4)
__global__ __launch_bounds__(256) void k_mlp(const float* __restrict__ w1,
                                             const float* __restrict__ b1,
                                             const float* __restrict__ w2,
                                             const float* __restrict__ b2,
                                             float* __restrict__ out) {
    extern __shared__ float sm[];
    float *Xs = sm;                // [128][68]
    float *Hs = Xs + 128*68;       // [64][68]
    float *Ws = Hs + 64*68;        // w1 chunk [128][68] or w2 chunk [64][132]
    int pt = blockIdx.x, n = blockIdx.y, tid = threadIdx.x, hw0 = pt*64;
    for (int l = tid; l < 128*16; l += 256) {
        int c = l>>4, p4 = (l&15)*4;
        float4 v = (c < 64) ? *(const float4*)&g_c[(n*ND+c)*NHW + hw0 + p4]
                            : *(const float4*)&g_b[(n*ND+c-64)*NHW + hw0 + p4];
        *(float4*)&Xs[c*68+p4] = v;
    }
    int fg = (tid>>4)*4, p0 = (tid&15)*4;
    int c8 = (tid>>4)*8;
    u64 accp[4][4];
    #pragma unroll
    for (int i = 0; i < 4; i++)
        for (int j = 0; j < 4; j++) accp[i][j] = 0ull;
    for (int fc = 0; fc < 8; fc++) {
        __syncthreads();
        for (int l = tid; l < 128*16; l += 256) {
            int c = l>>4, f4 = (l&15)*4;
            *(float4*)&Ws[c*68+f4] = *(const float4*)&w1[c*512 + fc*64 + f4];
        }
        __syncthreads();
        u64 a2p[2][4];
        #pragma unroll
        for (int i = 0; i < 2; i++)
            for (int j = 0; j < 4; j++) a2p[i][j] = 0ull;
        for (int c = 0; c < 128; c++) {
            float4 xq = *(const float4*)&Xs[c*68+p0];
            u64 bx[4] = {bc(xq.x), bc(xq.y), bc(xq.z), bc(xq.w)};
            u64 w01 = lds2(&Ws[c*68+fg]), w23 = lds2(&Ws[c*68+fg+2]);
            fma2(a2p[0][0], w01, bx[0]); fma2(a2p[0][1], w01, bx[1]);
            fma2(a2p[0][2], w01, bx[2]); fma2(a2p[0][3], w01, bx[3]);
            fma2(a2p[1][0], w23, bx[0]); fma2(a2p[1][1], w23, bx[1]);
            fma2(a2p[1][2], w23, bx[2]); fma2(a2p[1][3], w23, bx[3]);
        }
        __syncthreads();
        #pragma unroll
        for (int ip = 0; ip < 2; ip++) {
            int fA = fg + 2*ip, fB = fA + 1;
            float biasA = b1[fc*64 + fA], biasB = b1[fc*64 + fB];
            float2 v0 = up(a2p[ip][0]), v1 = up(a2p[ip][1]);
            float2 v2 = up(a2p[ip][2]), v3 = up(a2p[ip][3]);
            float4 hA = make_float4(gelu_f(v0.x + biasA), gelu_f(v1.x + biasA),
                                    gelu_f(v2.x + biasA), gelu_f(v3.x + biasA));
            float4 hB = make_float4(gelu_f(v0.y + biasB), gelu_f(v1.y + biasB),
                                    gelu_f(v2.y + biasB), gelu_f(v3.y + biasB));
            *(float4*)&Hs[fA*68 + p0] = hA;
            *(float4*)&Hs[fB*68 + p0] = hB;
        }
        for (int l = tid; l < 64*32; l += 256) {
            int f = l>>5, c4 = (l&31)*4;
            *(float4*)&Ws[f*132+c4] = *(const float4*)&w2[(fc*64+f)*128 + c4];
        }
        __syncthreads();
        for (int f = 0; f < 64; f++) {
            float4 hq = *(const float4*)&Hs[f*68+p0];
            u64 bh[4] = {bc(hq.x), bc(hq.y), bc(hq.z), bc(hq.w)};
            const u64* wp = (const u64*)&Ws[f*132+c8];
            #pragma unroll
            for (int ip = 0; ip < 4; ip++) {
                u64 wv = wp[ip];
                fma2(accp[ip][0], wv, bh[0]); fma2(accp[ip][1], wv, bh[1]);
                fma2(accp[ip][2], wv, bh[2]); fma2(accp[ip][3], wv, bh[3]);
            }
        }
    }
    #pragma unroll
    for (int ip = 0; ip < 4; ip++) {
        int cA = c8 + 2*ip, cB = cA + 1;
        float bA = b2[cA], bB = b2[cB];
        #pragma unroll
        for (int j = 0; j < 4; j++) {
            float2 v = up(accp[ip][j]);
            int p = p0 + j;
            float resA = (cA < 64) ? g_c[(n*ND+cA)*NHW + hw0 + p]
                                   : g_b[(n*ND+cA-64)*NHW + hw0 + p];
            float resB = (cB < 64) ? g_c[(n*ND+cB)*NHW + hw0 + p]
                                   : g_b[(n*ND+cB-64)*NHW + hw0 + p];
            out[((size_t)n*ND2 + cA)*NHW + hw0 + p] = v.x + bA + resA;
            out[((size_t)n*ND2 + cB)*NHW + hw0 + p] = v.y + bB + resB;
        }
    }
}

extern "C" void kernel_launch(void* const* d_in, const int* in_sizes, int n_in,
                              void* d_out, int out_size) {
    const float* xr   = (const float*)d_in[0];
    const float* xi   = (const float*)d_in[1];
    const float* dt   = (const float*)d_in[2];
    const float* lsg  = (const float*)d_in[3];
    const float* lsb  = (const float*)d_in[4];
    const float* cw   = (const float*)d_in[5];
    const float* cb   = (const float*)d_in[6];
    const float* swr  = (const float*)d_in[7];
    const float* swi  = (const float*)d_in[8];
    const float* gate = (const float*)d_in[9];
    const float* ltg  = (const float*)d_in[10];
    const float* ltb  = (const float*)d_in[11];
    const float* lamr = (const float*)d_in[12];
    const float* lami = (const float*)d_in[13];
    const float* enr  = (const float*)d_in[14];
    const float* eni  = (const float*)d_in[15];
    const float* dcr  = (const float*)d_in[16];
    const float* dci  = (const float*)d_in[17];
    const float* w1   = (const float*)d_in[18];
    const float* b1   = (const float*)d_in[19];
    const float* w2   = (const float*)d_in[20];
    const float* b2   = (const float*)d_in[21];
    float* out = (float*)d_out;

    cudaFuncSetAttribute(k_convfft,  cudaFuncAttributeMaxDynamicSharedMemorySize, CF_SM);
    cudaFuncSetAttribute(k_temporal, cudaFuncAttributeMaxDynamicSharedMemorySize, TEMP_SM);
    cudaFuncSetAttribute(k_mlp,      cudaFuncAttributeMaxDynamicSharedMemorySize, MLP_SM);

    dim3 gHN(64, 64);
    k_init<<<(128*128*9 + 255)/256, 256>>>(cw);
    k_ln0<<<gHN, dim3(64,4)>>>(xr, xi, lsg, lsb);
    k_convfft<<<6144, 256, CF_SM>>>(cb, swr, swi);
    k_comb<<<NTOT/1024, 256>>>(xr, xi, gate);
    k_temporal<<<dim3(64, NBB), 256, TEMP_SM>>>(enr, eni, dcr, dci, ltg, ltb, dt, lamr, lami);
    k_mlp<<<gHN, 256, MLP_SM>>>(w1, b1, w2, b2, out);
}

// round 17
// speedup vs baseline: 1.1770x; 1.0195x over previous
#include <cuda_runtime.h>
#include <math.h>

#define ND 64
#define ND2 128
#define NHW 4096
#define NBT 64
#define NTT 16
#define NBB 4
#define NTOT (NBT*ND*NHW)
#define PADW 66
#define PLANEP (PADW*PADW)
#define RP 66

typedef unsigned long long u64;

__device__ float g_pad[(size_t)NBT*ND2*PLANEP];   // zero-init: borders stay 0 forever
__device__ float g_a[NTOT], g_b[NTOT], g_c[NTOT], g_d[NTOT];
__device__ float g_w[128*128*9];                  // conv weights transposed [ic*9+tap][oc]
__device__ float g_twr[4096], g_twi[4096], g_twin[4096];  // DFT twiddles: cos, sin, -sin

// ---- f32x2 helpers ----
__device__ __forceinline__ u64 pk(float lo, float hi) {
    u64 r; asm("mov.b64 %0, {%1,%2};" : "=l"(r) : "f"(lo), "f"(hi)); return r;
}
__device__ __forceinline__ u64 bc(float v) { return pk(v, v); }
__device__ __forceinline__ void fma2(u64& d, u64 a, u64 b) {
    asm("fma.rn.f32x2 %0, %1, %2, %0;" : "+l"(d) : "l"(a), "l"(b));
}
__device__ __forceinline__ float2 up(u64 v) {
    float2 f; asm("mov.b64 {%0,%1}, %2;" : "=f"(f.x), "=f"(f.y) : "l"(v)); return f;
}
__device__ __forceinline__ u64 lds2(const float* p) { return *(const u64*)p; }
__device__ __forceinline__ u64 ldg2(const float* p) { return *(const u64*)p; }

// ---------- init ----------
__global__ void k_init(const float* __restrict__ cw) {
    int i = blockIdx.x*blockDim.x + threadIdx.x;
    if (i < 4096) {
        const float W64 = 6.28318530717958647692f/64.f;
        int u = i>>6, w = i&63, t = (u*w)&63;
        float sv, cv; sincosf(-W64*(float)t, &sv, &cv);
        g_twr[i] = cv; g_twi[i] = sv; g_twin[i] = -sv;
    }
    if (i < 128*128*9) {
        int oc = i / 1152, rem = i - oc*1152;
        g_w[rem*128 + oc] = cw[i];
    }
}

// ---------- spatial complex LayerNorm -> padded buffer ----------
__global__ void k_ln0(const float* __restrict__ xr, const float* __restrict__ xi,
                      const float* __restrict__ gam, const float* __restrict__ bet) {
    __shared__ float s[128][64];
    __shared__ float ps[4][64], pq[4][64], mb[64], rb[64];
    int h = blockIdx.x, n = blockIdx.y;
    int tx = threadIdx.x, ty = threadIdx.y;
    int base = n*(ND*NHW) + h*64 + tx;
    float sum = 0.f, sq = 0.f;
    for (int j = 0; j < 32; j++) {
        int c = ty*32 + j;
        float v = (c < 64) ? xr[base + c*NHW] : xi[base + (c-64)*NHW];
        s[c][tx] = v; sum += v; sq += v*v;
    }
    ps[ty][tx] = sum; pq[ty][tx] = sq;
    __syncthreads();
    if (ty == 0) {
        float S = ps[0][tx]+ps[1][tx]+ps[2][tx]+ps[3][tx];
        float Q = pq[0][tx]+pq[1][tx]+pq[2][tx]+pq[3][tx];
        float m = S*(1.f/128.f);
        mb[tx] = m; rb[tx] = rsqrtf(Q*(1.f/128.f) - m*m + 1e-5f);
    }
    __syncthreads();
    float m = mb[tx], r = rb[tx];
    for (int j = 0; j < 32; j++) {
        int c = ty*32 + j;
        float y = (s[c][tx] - m)*r*gam[c] + bet[c];
        g_pad[((size_t)(n*ND2 + c))*PLANEP + (h+1)*PADW + tx+1] = y;
    }
}

// ---------- merged conv(2 rows/block) + fft ----------
#define CF_SM ((4*16*68 + 16*9*128)*4)

__device__ __forceinline__ void conv_body(float* sm, int hb, int n,
                                          const float* __restrict__ cb) {
    float* sin_ = sm;              // [4][16][68]
    float* sw   = sm + 4*16*68;    // [16*9][128]
    int tid = threadIdx.x;
    int h0 = hb*2;
    const float* src = g_pad + (size_t)n*ND2*PLANEP;
    int wg = tid & 15, og = tid >> 4, w0 = wg*4;
    u64 accp[2][4][4];
    #pragma unroll
    for (int hh = 0; hh < 2; hh++)
        for (int a = 0; a < 4; a++)
            for (int b2 = 0; b2 < 4; b2++) accp[hh][a][b2] = 0ull;
    for (int icc = 0; icc < 8; icc++) {
        __syncthreads();
        for (int l = tid; l < 4*16*68; l += 256) {
            int r = l/(16*68), rem = l - r*(16*68);
            int icl = rem/68, c = rem - icl*68;
            sin_[l] = (c < 66) ? src[(size_t)(icc*16+icl)*PLANEP + (h0 + r)*PADW + c] : 0.f;
        }
        {
            const float4* wsrc = (const float4*)(g_w + icc*16*9*128);
            float4* wdst = (float4*)sw;
            for (int l = tid; l < 16*9*128/4; l += 256)
                wdst[l] = wsrc[l];
        }
        __syncthreads();
        #pragma unroll 1
        for (int icl = 0; icl < 16; icl++) {
            float inv[4][6];
            #pragma unroll
            for (int r = 0; r < 4; r++) {
                const float* rp = &sin_[(r*16+icl)*68 + w0];
                float4 q = *(const float4*)rp;
                float2 t = *(const float2*)(rp+4);
                inv[r][0]=q.x; inv[r][1]=q.y; inv[r][2]=q.z;
                inv[r][3]=q.w; inv[r][4]=t.x; inv[r][5]=t.y;
            }
            #pragma unroll
            for (int ky = 0; ky < 3; ky++)
                for (int kx = 0; kx < 3; kx++) {
                    int tap = ky*3 + kx;
                    const u64* wp = (const u64*)&sw[(icl*9+tap)*128 + og*8];
                    u64 wv0 = wp[0], wv1 = wp[1], wv2 = wp[2], wv3 = wp[3];
                    #pragma unroll
                    for (int hh = 0; hh < 2; hh++) {
                        u64 b0 = bc(inv[ky+hh][kx]),   b1 = bc(inv[ky+hh][kx+1]);
                        u64 b2 = bc(inv[ky+hh][kx+2]), b3 = bc(inv[ky+hh][kx+3]);
                        fma2(accp[hh][0][0], wv0, b0); fma2(accp[hh][0][1], wv0, b1);
                        fma2(accp[hh][0][2], wv0, b2); fma2(accp[hh][0][3], wv0, b3);
                        fma2(accp[hh][1][0], wv1, b0); fma2(accp[hh][1][1], wv1, b1);
                        fma2(accp[hh][1][2], wv1, b2); fma2(accp[hh][1][3], wv1, b3);
                        fma2(accp[hh][2][0], wv2, b0); fma2(accp[hh][2][1], wv2, b1);
                        fma2(accp[hh][2][2], wv2, b2); fma2(accp[hh][2][3], wv2, b3);
                        fma2(accp[hh][3][0], wv3, b0); fma2(accp[hh][3][1], wv3, b1);
                        fma2(accp[hh][3][2], wv3, b2); fma2(accp[hh][3][3], wv3, b3);
                    }
                }
        }
    }
    #pragma unroll
    for (int hh = 0; hh < 2; hh++) {
        int ob = n*(ND*NHW) + (h0+hh)*64 + w0;
        #pragma unroll
        for (int op = 0; op < 4; op++) {
            int oc0 = og*8 + 2*op;
            float bia0 = cb[oc0], bia1 = cb[oc0+1];
            float2 v0 = up(accp[hh][op][0]), v1 = up(accp[hh][op][1]);
            float2 v2 = up(accp[hh][op][2]), v3 = up(accp[hh][op][3]);
            float4 a4 = make_float4(v0.x+bia0, v1.x+bia0, v2.x+bia0, v3.x+bia0);
            float4 b4 = make_float4(v0.y+bia1, v1.y+bia1, v2.y+bia1, v3.y+bia1);
            if (oc0 < 64) {
                *(float4*)&g_a[ob + oc0*NHW]     = a4;
                *(float4*)&g_a[ob + (oc0+1)*NHW] = b4;
            } else {
                *(float4*)&g_b[ob + (oc0-64)*NHW] = a4;
                *(float4*)&g_b[ob + (oc0-63)*NHW] = b4;
            }
        }
    }
}

__device__ __forceinline__ void fft_body(float* sm, int d, int n,
                                         const float* __restrict__ swr,
                                         const float* __restrict__ swi) {
    float *ar = sm, *ai = ar+64*RP, *br = ai+64*RP, *bi = br+64*RP;
    int tid = threadIdx.x;
    const float* pr0 = g_pad + ((size_t)(n*ND2 + d))*PLANEP;
    const float* pi0 = g_pad + ((size_t)(n*ND2 + 64 + d))*PLANEP;
    for (int l = tid; l < 4096; l += 256) {
        int hh = l>>6, ww = l&63;
        ar[hh*RP+ww] = pr0[(hh+1)*PADW + ww+1];
        ai[hh*RP+ww] = pi0[(hh+1)*PADW + ww+1];
    }
    __syncthreads();
    int r0 = (tid>>4)*4, c0 = (tid&15)*4;
    { // pass1
        u64 pr_[4][2] = {}, pi_[4][2] = {};
        for (int w = 0; w < 64; w++) {
            u64 g0 = ldg2(&g_twr[w*64+c0]),  g1 = ldg2(&g_twr[w*64+c0+2]);
            u64 q0 = ldg2(&g_twi[w*64+c0]),  q1 = ldg2(&g_twi[w*64+c0+2]);
            u64 n0 = ldg2(&g_twin[w*64+c0]), n1 = ldg2(&g_twin[w*64+c0+2]);
            #pragma unroll
            for (int i = 0; i < 4; i++) {
                float xr1 = ar[(r0+i)*RP+w], xi1 = ai[(r0+i)*RP+w];
                u64 bxr = bc(xr1), bxi = bc(xi1);
                fma2(pr_[i][0], bxr, g0); fma2(pr_[i][0], bxi, n0);
                fma2(pr_[i][1], bxr, g1); fma2(pr_[i][1], bxi, n1);
                fma2(pi_[i][0], bxr, q0); fma2(pi_[i][0], bxi, g0);
                fma2(pi_[i][1], bxr, q1); fma2(pi_[i][1], bxi, g1);
            }
        }
        #pragma unroll
        for (int i = 0; i < 4; i++) {
            *(float2*)&br[(r0+i)*RP+c0]   = up(pr_[i][0]);
            *(float2*)&br[(r0+i)*RP+c0+2] = up(pr_[i][1]);
            *(float2*)&bi[(r0+i)*RP+c0]   = up(pi_[i][0]);
            *(float2*)&bi[(r0+i)*RP+c0+2] = up(pi_[i][1]);
        }
    }
    __syncthreads();
    { // pass2
        u64 pr_[4][2] = {}, pi_[4][2] = {};
        for (int hs = 0; hs < 64; hs++) {
            u64 x0 = lds2(&br[hs*RP+c0]), x1 = lds2(&br[hs*RP+c0+2]);
            u64 y0 = lds2(&bi[hs*RP+c0]), y1 = lds2(&bi[hs*RP+c0+2]);
            float2 ga = *(const float2*)&g_twr[hs*64+r0],  gb2 = *(const float2*)&g_twr[hs*64+r0+2];
            float2 qa = *(const float2*)&g_twi[hs*64+r0],  qb = *(const float2*)&g_twi[hs*64+r0+2];
            float2 na = *(const float2*)&g_twin[hs*64+r0], nb = *(const float2*)&g_twin[hs*64+r0+2];
            float grs[4] = {ga.x, ga.y, gb2.x, gb2.y};
            float gis[4] = {qa.x, qa.y, qb.x, qb.y};
            float gns[4] = {na.x, na.y, nb.x, nb.y};
            #pragma unroll
            for (int i = 0; i < 4; i++) {
                u64 bgr = bc(grs[i]), bgi = bc(gis[i]), bgn = bc(gns[i]);
                fma2(pr_[i][0], bgr, x0); fma2(pr_[i][0], bgn, y0);
                fma2(pr_[i][1], bgr, x1); fma2(pr_[i][1], bgn, y1);
                fma2(pi_[i][0], bgr, y0); fma2(pi_[i][0], bgi, x0);
                fma2(pi_[i][1], bgr, y1); fma2(pi_[i][1], bgi, x1);
            }
        }
        __syncthreads();
        #pragma unroll
        for (int i = 0; i < 4; i++) {
            *(float2*)&ar[(r0+i)*RP+c0]   = up(pr_[i][0]);
            *(float2*)&ar[(r0+i)*RP+c0+2] = up(pr_[i][1]);
            *(float2*)&ai[(r0+i)*RP+c0]   = up(pi_[i][0]);
            *(float2*)&ai[(r0+i)*RP+c0+2] = up(pi_[i][1]);
        }
    }
    __syncthreads();
    { // pointwise * spec_w[d]
        const float* wr2 = swr + d*NHW; const float* wi2 = swi + d*NHW;
        for (int l = tid; l < 4096; l += 256) {
            int u = l>>6, v = l&63;
            float zr = ar[u*RP+v], zi = ai[u*RP+v];
            float wr_ = wr2[l], wi_ = wi2[l];
            ar[u*RP+v] = zr*wr_ - zi*wi_;
            ai[u*RP+v] = zr*wi_ + zi*wr_;
        }
    }
    __syncthreads();
    { // pass3 (conj)
        u64 pr_[4][2] = {}, pi_[4][2] = {};
        for (int us = 0; us < 64; us++) {
            u64 x0 = lds2(&ar[us*RP+c0]), x1 = lds2(&ar[us*RP+c0+2]);
            u64 y0 = lds2(&ai[us*RP+c0]), y1 = lds2(&ai[us*RP+c0+2]);
            float2 ga = *(const float2*)&g_twr[us*64+r0],  gb2 = *(const float2*)&g_twr[us*64+r0+2];
            float2 qa = *(const float2*)&g_twi[us*64+r0],  qb = *(const float2*)&g_twi[us*64+r0+2];
            float2 na = *(const float2*)&g_twin[us*64+r0], nb = *(const float2*)&g_twin[us*64+r0+2];
            float grs[4] = {ga.x, ga.y, gb2.x, gb2.y};
            float gis[4] = {qa.x, qa.y, qb.x, qb.y};
            float gns[4] = {na.x, na.y, nb.x, nb.y};
            #pragma unroll
            for (int i = 0; i < 4; i++) {
                u64 bgr = bc(grs[i]), bgi = bc(gis[i]), bgn = bc(gns[i]);
                fma2(pr_[i][0], bgr, x0); fma2(pr_[i][0], bgi, y0);
                fma2(pr_[i][1], bgr, x1); fma2(pr_[i][1], bgi, y1);
                fma2(pi_[i][0], bgr, y0); fma2(pi_[i][0], bgn, x0);
                fma2(pi_[i][1], bgr, y1); fma2(pi_[i][1], bgn, x1);
            }
        }
        #pragma unroll
        for (int i = 0; i < 4; i++) {
            *(float2*)&br[(r0+i)*RP+c0]   = up(pr_[i][0]);
            *(float2*)&br[(r0+i)*RP+c0+2] = up(pr_[i][1]);
            *(float2*)&bi[(r0+i)*RP+c0]   = up(pi_[i][0]);
            *(float2*)&bi[(r0+i)*RP+c0+2] = up(pi_[i][1]);
        }
    }
    __syncthreads();
    { // pass4 -> spec (scaled) into g_c/g_d
        u64 pr_[4][2] = {}, pi_[4][2] = {};
        for (int vs = 0; vs < 64; vs++) {
            u64 g0 = ldg2(&g_twr[vs*64+c0]),  g1 = ldg2(&g_twr[vs*64+c0+2]);
            u64 q0 = ldg2(&g_twi[vs*64+c0]),  q1 = ldg2(&g_twi[vs*64+c0+2]);
            u64 n0 = ldg2(&g_twin[vs*64+c0]), n1 = ldg2(&g_twin[vs*64+c0+2]);
            #pragma unroll
            for (int i = 0; i < 4; i++) {
                float xr1 = br[(r0+i)*RP+vs], xi1 = bi[(r0+i)*RP+vs];
                u64 bxr = bc(xr1), bxi = bc(xi1);
                fma2(pr_[i][0], bxr, g0); fma2(pr_[i][0], bxi, q0);
                fma2(pr_[i][1], bxr, g1); fma2(pr_[i][1], bxi, q1);
                fma2(pi_[i][0], bxi, g0); fma2(pi_[i][0], bxr, n0);
                fma2(pi_[i][1], bxi, g1); fma2(pi_[i][1], bxr, n1);
            }
        }
        const float sc = 1.f/4096.f;
        int base = n*ND*NHW + d*NHW;
        #pragma unroll
        for (int i = 0; i < 4; i++)
            for (int jp = 0; jp < 2; jp++) {
                int idx = base + (r0+i)*64 + c0 + 2*jp;
                float2 sr = up(pr_[i][jp]);
                float2 si = up(pi_[i][jp]);
                sr.x *= sc; sr.y *= sc; si.x *= sc; si.y *= sc;
                *(float2*)&g_c[idx] = sr;
                *(float2*)&g_d[idx] = si;
            }
    }
}

__global__ __launch_bounds__(256, 2) void k_convfft(const float* __restrict__ cb,
                                                    const float* __restrict__ swr,
                                                    const float* __restrict__ swi) {
    extern __shared__ float sm[];
    int bid = blockIdx.x;
    int grp = bid / 3, rem = bid - grp*3;
    if (rem == 0) {
        conv_body(sm, grp & 31, grp >> 5, cb);
    } else {
        int f = grp*2 + (rem - 1);
        fft_body(sm, f & 63, f >> 6, swr, swi);
    }
}

// ---------- fused temporal branch: combine + LN + encode + recurrence + decode ----------
// combine (x1 = g*cliff + (1-g)*spec + x_in) fused into the load; x1 written back to g_a/g_b.
#define TEMP_SM (6*64*RP*4)
__global__ __launch_bounds__(256, 2) void k_temporal(
        const float* __restrict__ er, const float* __restrict__ ei,
        const float* __restrict__ dmr, const float* __restrict__ dmi,
        const float* __restrict__ gam, const float* __restrict__ bet,
        const float* __restrict__ dt,  const float* __restrict__ lr_,
        const float* __restrict__ li_,
        const float* __restrict__ xin_r, const float* __restrict__ xin_i,
        const float* __restrict__ gate) {
    extern __shared__ float sm[];
    float *Er = sm, *Ei = Er+64*RP, *Dr = Ei+64*RP, *Di = Dr+64*RP;
    float *Xr = Di+64*RP, *Xi = Xr+64*RP;
    __shared__ float ps[16][64], pq[16][64], mb[64], rb[64];
    int pt = blockIdx.x, b = blockIdx.y, tid = threadIdx.x, hw0 = pt*64;
    for (int l = tid; l < 4096; l += 256) {
        int r_ = l>>6, c_ = l&63;
        Er[r_*RP+c_] = er[l];  Ei[r_*RP+c_] = ei[l];
        Dr[r_*RP+c_] = dmr[l]; Di[r_*RP+c_] = dmi[l];
    }
    int e0 = (tid>>4)*4, p0 = (tid&15)*4;
    int gq = tid>>4, q = tid&15, p4 = q*4;
    float gate_g = gate[0], gate_o = 1.f - gate_g;
    float ddr[4], ddi[4], ffr[4], ffi[4];
    float dtb = dt[b];
    #pragma unroll
    for (int i = 0; i < 4; i++) {
        float lr = lr_[e0+i], li = li_[e0+i];
        float ex = expf(lr*dtb);
        float sn, cs; sincosf(li*dtb, &sn, &cs);
        ddr[i] = ex*cs; ddi[i] = ex*sn;
        float nr = ddr[i]-1.f, ni = ddi[i];
        float den = 1.f/(lr*lr + li*li);
        ffr[i] = (nr*lr + ni*li)*den;
        ffi[i] = (ni*lr - nr*li)*den;
    }
    u64 hrp[4][2] = {}, hip[4][2] = {};
    for (int t = 0; t < NTT; t++) {
        int n = b*NTT + t;
        __syncthreads();   // Xr/Xi free (prev GEMM-D done)
        // fused combine + stats; keep x1 in registers across the stats barrier
        float4 vr4[4], vi4[4];
        float s4[4] = {0.f,0.f,0.f,0.f}, q4[4] = {0.f,0.f,0.f,0.f};
        #pragma unroll
        for (int k = 0; k < 4; k++) {
            int dd = gq + k*16;
            int gi_ = (n*ND+dd)*NHW + hw0 + p4;
            float4 cl = *(const float4*)&g_a[gi_];
            float4 sp = *(const float4*)&g_c[gi_];
            float4 xn = *(const float4*)&xin_r[gi_];
            float4 vr;
            vr.x = gate_g*cl.x + gate_o*sp.x + xn.x;
            vr.y = gate_g*cl.y + gate_o*sp.y + xn.y;
            vr.z = gate_g*cl.z + gate_o*sp.z + xn.z;
            vr.w = gate_g*cl.w + gate_o*sp.w + xn.w;
            float4 ci = *(const float4*)&g_b[gi_];
            float4 si = *(const float4*)&g_d[gi_];
            float4 yn = *(const float4*)&xin_i[gi_];
            float4 vi;
            vi.x = gate_g*ci.x + gate_o*si.x + yn.x;
            vi.y = gate_g*ci.y + gate_o*si.y + yn.y;
            vi.z = gate_g*ci.z + gate_o*si.z + yn.z;
            vi.w = gate_g*ci.w + gate_o*si.w + yn.w;
            *(float4*)&g_a[gi_] = vr;   // x1 materialized for decode-resid + mlp
            *(float4*)&g_b[gi_] = vi;
            vr4[k] = vr; vi4[k] = vi;
            s4[0] += vr.x + vi.x; q4[0] += vr.x*vr.x + vi.x*vi.x;
            s4[1] += vr.y + vi.y; q4[1] += vr.y*vr.y + vi.y*vi.y;
            s4[2] += vr.z + vi.z; q4[2] += vr.z*vr.z + vi.z*vi.z;
            s4[3] += vr.w + vi.w; q4[3] += vr.w*vr.w + vi.w*vi.w;
        }
        #pragma unroll
        for (int j = 0; j < 4; j++) { ps[gq][p4+j] = s4[j]; pq[gq][p4+j] = q4[j]; }
        __syncthreads();
        if (tid < 64) {
            float S = 0.f, Q = 0.f;
            #pragma unroll
            for (int g2 = 0; g2 < 16; g2++) { S += ps[g2][tid]; Q += pq[g2][tid]; }
            float m = S*(1.f/128.f);
            mb[tid] = m; rb[tid] = rsqrtf(Q*(1.f/128.f) - m*m + 1e-5f);
        }
        __syncthreads();
        {   // normalize in registers, single smem store
            float4 m4 = *(const float4*)&mb[p4];
            float4 r4 = *(const float4*)&rb[p4];
            #pragma unroll
            for (int k = 0; k < 4; k++) {
                int dd = gq + k*16;
                float gr = gam[dd], br_ = bet[dd];
                float gi2 = gam[dd+64], bi2 = bet[dd+64];
                float4 vr = vr4[k], vi = vi4[k];
                vr.x = (vr.x - m4.x)*r4.x*gr + br_;
                vr.y = (vr.y - m4.y)*r4.y*gr + br_;
                vr.z = (vr.z - m4.z)*r4.z*gr + br_;
                vr.w = (vr.w - m4.w)*r4.w*gr + br_;
                vi.x = (vi.x - m4.x)*r4.x*gi2 + bi2;
                vi.y = (vi.y - m4.y)*r4.y*gi2 + bi2;
                vi.z = (vi.z - m4.z)*r4.z*gi2 + bi2;
                vi.w = (vi.w - m4.w)*r4.w*gi2 + bi2;
                *(float2*)&Xr[dd*RP+p4]   = make_float2(vr.x, vr.y);
                *(float2*)&Xr[dd*RP+p4+2] = make_float2(vr.z, vr.w);
                *(float2*)&Xi[dd*RP+p4]   = make_float2(vi.x, vi.y);
                *(float2*)&Xi[dd*RP+p4+2] = make_float2(vi.z, vi.w);
            }
        }
        __syncthreads();
        // GEMM-E
        u64 pr_[4][2] = {}, pi_[4][2] = {};
        for (int dd = 0; dd < 64; dd++) {
            u64 x0 = lds2(&Xr[dd*RP+p0]), x1 = lds2(&Xr[dd*RP+p0+2]);
            u64 y0 = lds2(&Xi[dd*RP+p0]), y1 = lds2(&Xi[dd*RP+p0+2]);
            float2 ea = *(const float2*)&Er[dd*RP+e0], eb = *(const float2*)&Er[dd*RP+e0+2];
            float2 qa = *(const float2*)&Ei[dd*RP+e0], qb = *(const float2*)&Ei[dd*RP+e0+2];
            float ers[4] = {ea.x, ea.y, eb.x, eb.y};
            float eis[4] = {qa.x, qa.y, qb.x, qb.y};
            #pragma unroll
            for (int i = 0; i < 4; i++) {
                u64 ber = bc(ers[i]), bei = bc(eis[i]), bnei = bc(-eis[i]);
                fma2(pr_[i][0], x0, ber); fma2(pr_[i][0], y0, bnei);
                fma2(pr_[i][1], x1, ber); fma2(pr_[i][1], y1, bnei);
                fma2(pi_[i][0], x0, bei); fma2(pi_[i][0], y0, ber);
                fma2(pi_[i][1], x1, bei); fma2(pi_[i][1], y1, ber);
            }
        }
        // recurrence in registers
        #pragma unroll
        for (int i = 0; i < 4; i++) {
            u64 bdr = bc(ddr[i]), bdi = bc(ddi[i]), bndi = bc(-ddi[i]);
            u64 bfr = bc(ffr[i]), bfi = bc(ffi[i]), bnfi = bc(-ffi[i]);
            #pragma unroll
            for (int jp = 0; jp < 2; jp++) {
                u64 nr_ = 0ull, ni_ = 0ull;
                fma2(nr_, hrp[i][jp], bdr); fma2(nr_, hip[i][jp], bndi);
                fma2(nr_, pr_[i][jp], bfr); fma2(nr_, pi_[i][jp], bnfi);
                fma2(ni_, hrp[i][jp], bdi); fma2(ni_, hip[i][jp], bdr);
                fma2(ni_, pr_[i][jp], bfi); fma2(ni_, pi_[i][jp], bfr);
                hrp[i][jp] = nr_; hip[i][jp] = ni_;
            }
        }
        __syncthreads();
        #pragma unroll
        for (int i = 0; i < 4; i++)
            for (int jp = 0; jp < 2; jp++) {
                *(float2*)&Xr[(e0+i)*RP + p0 + 2*jp] = up(hrp[i][jp]);
                *(float2*)&Xi[(e0+i)*RP + p0 + 2*jp] = up(hip[i][jp]);
            }
        __syncthreads();
        // GEMM-D (real) + residual, float4 epilogue
        u64 acc[4][2] = {};
        for (int e = 0; e < 64; e++) {
            u64 x0 = lds2(&Xr[e*RP+p0]), x1 = lds2(&Xr[e*RP+p0+2]);
            u64 y0 = lds2(&Xi[e*RP+p0]), y1 = lds2(&Xi[e*RP+p0+2]);
            float2 da = *(const float2*)&Dr[e*RP+e0], db = *(const float2*)&Dr[e*RP+e0+2];
            float2 qa = *(const float2*)&Di[e*RP+e0], qb = *(const float2*)&Di[e*RP+e0+2];
            float drs[4] = {da.x, da.y, db.x, db.y};
            float dis[4] = {qa.x, qa.y, qb.x, qb.y};
            #pragma unroll
            for (int i = 0; i < 4; i++) {
                u64 bdr = bc(drs[i]), bnd = bc(-dis[i]);
                fma2(acc[i][0], x0, bdr); fma2(acc[i][0], y0, bnd);
                fma2(acc[i][1], x1, bdr); fma2(acc[i][1], y1, bnd);
            }
        }
        #pragma unroll
        for (int i = 0; i < 4; i++) {
            int gi_ = (n*ND + e0+i)*NHW + hw0 + p0;
            float2 va = up(acc[i][0]), vb = up(acc[i][1]);
            float4 rs = *(const float4*)&g_a[gi_];
            float4 o = make_float4(va.x+rs.x, va.y+rs.y, vb.x+rs.z, vb.y+rs.w);
            *(float4*)&g_c[gi_] = o;
        }
    }
}

// ---------- fast gelu ----------
__device__ __forceinline__ float gelu_f(float x) {
    float u = 0.7978845608028654f*(x + 0.044715f*x*x*x);
    return x * (1.f - __fdividef(1.f, __expf(2.f*u) + 1.f));
}

// ---------- fused MLP 128 -> 512(gelu) -> 128 + residual, f chunked by 64 ----------
#define MLP_SM ((128*68 + 64*68 + 8704)*4)
__global__ __launch_bounds__(256) void k_mlp(const float* __restrict__ w1,
                                             const float* __restrict__ b1,
                                             const float* __restrict__ w2,
                                             const float* __restrict__ b2,
                                             float* __restrict__ out) {
    extern __shared__ float sm[];
    float *Xs = sm;                // [128][68]
    float *Hs = Xs + 128*68;       // [64][68]
    float *Ws = Hs + 64*68;        // w1 chunk [128][68] or w2 chunk [64][132]
    int pt = blockIdx.x, n = blockIdx.y, tid = threadIdx.x, hw0 = pt*64;
    for (int l = tid; l < 128*16; l += 256) {
        int c = l>>4, p4 = (l&15)*4;
        float4 v = (c < 64) ? *(const float4*)&g_c[(n*ND+c)*NHW + hw0 + p4]
                            : *(const float4*)&g_b[(n*ND+c-64)*NHW + hw0 + p4];
        *(float4*)&Xs[c*68+p4] = v;
    }
    int fg = (tid>>4)*4, p0 = (tid&15)*4;
    int c8 = (tid>>4)*8;
    u64 accp[4][4];
    #pragma unroll
    for (int i = 0; i < 4; i++)
        for (int j = 0; j < 4; j++) accp[i][j] = 0ull;
    for (int fc = 0; fc < 8; fc++) {
        __syncthreads();
        for (int l = tid; l < 128*16; l += 256) {
            int c = l>>4, f4 = (l&15)*4;
            *(float4*)&Ws[c*68+f4] = *(const float4*)&w1[c*512 + fc*64 + f4];
        }
        __syncthreads();
        u64 a2p[2][4];
        #pragma unroll
        for (int i = 0; i < 2; i++)
            for (int j = 0; j < 4; j++) a2p[i][j] = 0ull;
        for (int c = 0; c < 128; c++) {
            float4 xq = *(const float4*)&Xs[c*68+p0];
            u64 bx[4] = {bc(xq.x), bc(xq.y), bc(xq.z), bc(xq.w)};
            u64 w01 = lds2(&Ws[c*68+fg]), w23 = lds2(&Ws[c*68+fg+2]);
            fma2(a2p[0][0], w01, bx[0]); fma2(a2p[0][1], w01, bx[1]);
            fma2(a2p[0][2], w01, bx[2]); fma2(a2p[0][3], w01, bx[3]);
            fma2(a2p[1][0], w23, bx[0]); fma2(a2p[1][1], w23, bx[1]);
            fma2(a2p[1][2], w23, bx[2]); fma2(a2p[1][3], w23, bx[3]);
        }
        __syncthreads();
        #pragma unroll
        for (int ip = 0; ip < 2; ip++) {
            int fA = fg + 2*ip, fB = fA + 1;
            float biasA = b1[fc*64 + fA], biasB = b1[fc*64 + fB];
            float2 v0 = up(a2p[ip][0]), v1 = up(a2p[ip][1]);
            float2 v2 = up(a2p[ip][2]), v3 = up(a2p[ip][3]);
            float4 hA = make_float4(gelu_f(v0.x + biasA), gelu_f(v1.x + biasA),
                                    gelu_f(v2.x + biasA), gelu_f(v3.x + biasA));
            float4 hB = make_float4(gelu_f(v0.y + biasB), gelu_f(v1.y + biasB),
                                    gelu_f(v2.y + biasB), gelu_f(v3.y + biasB));
            *(float4*)&Hs[fA*68 + p0] = hA;
            *(float4*)&Hs[fB*68 + p0] = hB;
        }
        for (int l = tid; l < 64*32; l += 256) {
            int f = l>>5, c4 = (l&31)*4;
            *(float4*)&Ws[f*132+c4] = *(const float4*)&w2[(fc*64+f)*128 + c4];
        }
        __syncthreads();
        for (int f = 0; f < 64; f++) {
            float4 hq = *(const float4*)&Hs[f*68+p0];
            u64 bh[4] = {bc(hq.x), bc(hq.y), bc(hq.z), bc(hq.w)};
            const u64* wp = (const u64*)&Ws[f*132+c8];
            #pragma unroll
            for (int ip = 0; ip < 4; ip++) {
                u64 wv = wp[ip];
                fma2(accp[ip][0], wv, bh[0]); fma2(accp[ip][1], wv, bh[1]);
                fma2(accp[ip][2], wv, bh[2]); fma2(accp[ip][3], wv, bh[3]);
            }
        }
    }
    #pragma unroll
    for (int ip = 0; ip < 4; ip++) {
        int cA = c8 + 2*ip, cB = cA + 1;
        float bA = b2[cA], bB = b2[cB];
        float2 v0 = up(accp[ip][0]), v1 = up(accp[ip][1]);
        float2 v2 = up(accp[ip][2]), v3 = up(accp[ip][3]);
        float4 resA = (cA < 64) ? *(const float4*)&g_c[(n*ND+cA)*NHW + hw0 + p0]
                                : *(const float4*)&g_b[(n*ND+cA-64)*NHW + hw0 + p0];
        float4 resB = (cB < 64) ? *(const float4*)&g_c[(n*ND+cB)*NHW + hw0 + p0]
                                : *(const float4*)&g_b[(n*ND+cB-64)*NHW + hw0 + p0];
        float4 oA = make_float4(v0.x+bA+resA.x, v1.x+bA+resA.y, v2.x+bA+resA.z, v3.x+bA+resA.w);
        float4 oB = make_float4(v0.y+bB+resB.x, v1.y+bB+resB.y, v2.y+bB+resB.z, v3.y+bB+resB.w);
        *(float4*)&out[((size_t)n*ND2 + cA)*NHW + hw0 + p0] = oA;
        *(float4*)&out[((size_t)n*ND2 + cB)*NHW + hw0 + p0] = oB;
    }
}

extern "C" void kernel_launch(void* const* d_in, const int* in_sizes, int n_in,
                              void* d_out, int out_size) {
    const float* xr   = (const float*)d_in[0];
    const float* xi   = (const float*)d_in[1];
    const float* dt   = (const float*)d_in[2];
    const float* lsg  = (const float*)d_in[3];
    const float* lsb  = (const float*)d_in[4];
    const float* cw   = (const float*)d_in[5];
    const float* cb   = (const float*)d_in[6];
    const float* swr  = (const float*)d_in[7];
    const float* swi  = (const float*)d_in[8];
    const float* gate = (const float*)d_in[9];
    const float* ltg  = (const float*)d_in[10];
    const float* ltb  = (const float*)d_in[11];
    const float* lamr = (const float*)d_in[12];
    const float* lami = (const float*)d_in[13];
    const float* enr  = (const float*)d_in[14];
    const float* eni  = (const float*)d_in[15];
    const float* dcr  = (const float*)d_in[16];
    const float* dci  = (const float*)d_in[17];
    const float* w1   = (const float*)d_in[18];
    const float* b1   = (const float*)d_in[19];
    const float* w2   = (const float*)d_in[20];
    const float* b2   = (const float*)d_in[21];
    float* out = (float*)d_out;

    cudaFuncSetAttribute(k_convfft,  cudaFuncAttributeMaxDynamicSharedMemorySize, CF_SM);
    cudaFuncSetAttribute(k_temporal, cudaFuncAttributeMaxDynamicSharedMemorySize, TEMP_SM);
    cudaFuncSetAttribute(k_mlp,      cudaFuncAttributeMaxDynamicSharedMemorySize, MLP_SM);

    dim3 gHN(64, 64);
    k_init<<<(128*128*9 + 255)/256, 256>>>(cw);
    k_ln0<<<gHN, dim3(64,4)>>>(xr, xi, lsg, lsb);
    k_convfft<<<6144, 256, CF_SM>>>(cb, swr, swi);
    k_temporal<<<dim3(64, NBB), 256, TEMP_SM>>>(enr, eni, dcr, dci, ltg, ltb, dt,
                                                lamr, lami, xr, xi, gate);
    k_mlp<<<gHN, 256, MLP_SM>>>(w1, b1, w2, b2, out);
}